// round 1
// baseline (speedup 1.0000x reference)
#include <cuda_runtime.h>
#include <math.h>

#define S_LEN   4096
#define BATCH   2
#define DMODEL  1024
#define DFF     256
#define M_ROWS  (S_LEN * BATCH)   // 8192

// Scratch for Q, K, V projections: [8192][256] fp32 each (8 MB each).
__device__ float Qg[M_ROWS * DFF];
__device__ float Kg[M_ROWS * DFF];
__device__ float Vg[M_ROWS * DFF];

// ---------------------------------------------------------------------------
// Kernel 1: QKV projection.  C[8192,256] = X[8192,1024] * W[1024,256]
// blockIdx.z selects (W_q->Qg, W_k->Kg, W_v->Vg).
// 128x128x16 tile, 256 threads, 8x8 per-thread micro-tile, register prefetch.
// ---------------------------------------------------------------------------
#define BM 128
#define BN 128
#define BK 16

__global__ __launch_bounds__(256) void proj_kernel(
    const float* __restrict__ X,
    const float* __restrict__ Wq,
    const float* __restrict__ Wk,
    const float* __restrict__ Wv)
{
    __shared__ float As[BK][BM + 4];   // transposed: As[k][m]
    __shared__ float Bs[BK][BN + 4];   // Bs[k][n]

    const float* W;
    float* Out;
    if (blockIdx.z == 0)      { W = Wq; Out = Qg; }
    else if (blockIdx.z == 1) { W = Wk; Out = Kg; }
    else                      { W = Wv; Out = Vg; }

    const int t  = threadIdx.x;
    const int m0 = blockIdx.x * BM;
    const int n0 = blockIdx.y * BN;

    // Load-index precompute (2 float4 per thread per tile, for A and for B)
    int arow[2], ac[2], brow[2], bc[2];
#pragma unroll
    for (int i = 0; i < 2; i++) {
        int f = t + 256 * i;
        arow[i] = f >> 2;          // 0..127
        ac[i]   = (f & 3) * 4;     // 0,4,8,12
        brow[i] = f >> 5;          // 0..15
        bc[i]   = (f & 31) * 4;    // 0..124
    }

    float4 pa[2], pb[2];
#pragma unroll
    for (int i = 0; i < 2; i++) {
        pa[i] = *(const float4*)&X[(m0 + arow[i]) * DMODEL + ac[i]];
        pb[i] = *(const float4*)&W[brow[i] * DFF + n0 + bc[i]];
    }

    float acc[8][8];
#pragma unroll
    for (int i = 0; i < 8; i++)
#pragma unroll
        for (int j = 0; j < 8; j++) acc[i][j] = 0.f;

    const int ty = t >> 4;   // 0..15
    const int tx = t & 15;   // 0..15

    const int NKT = DMODEL / BK;   // 64
    for (int kt = 0; kt < NKT; kt++) {
        // stage prefetched tile into smem
#pragma unroll
        for (int i = 0; i < 2; i++) {
            As[ac[i] + 0][arow[i]] = pa[i].x;
            As[ac[i] + 1][arow[i]] = pa[i].y;
            As[ac[i] + 2][arow[i]] = pa[i].z;
            As[ac[i] + 3][arow[i]] = pa[i].w;
            *(float4*)&Bs[brow[i]][bc[i]] = pb[i];
        }
        __syncthreads();

        // prefetch next tile (hidden under compute)
        if (kt + 1 < NKT) {
            int k0 = (kt + 1) * BK;
#pragma unroll
            for (int i = 0; i < 2; i++) {
                pa[i] = *(const float4*)&X[(m0 + arow[i]) * DMODEL + k0 + ac[i]];
                pb[i] = *(const float4*)&W[(k0 + brow[i]) * DFF + n0 + bc[i]];
            }
        }

#pragma unroll
        for (int kk = 0; kk < BK; kk++) {
            float4 a0 = *(const float4*)&As[kk][ty * 8];
            float4 a1 = *(const float4*)&As[kk][ty * 8 + 4];
            float4 b0 = *(const float4*)&Bs[kk][tx * 8];
            float4 b1 = *(const float4*)&Bs[kk][tx * 8 + 4];
            float a[8] = {a0.x, a0.y, a0.z, a0.w, a1.x, a1.y, a1.z, a1.w};
            float b[8] = {b0.x, b0.y, b0.z, b0.w, b1.x, b1.y, b1.z, b1.w};
#pragma unroll
            for (int i = 0; i < 8; i++)
#pragma unroll
                for (int j = 0; j < 8; j++)
                    acc[i][j] += a[i] * b[j];
        }
        __syncthreads();
    }

#pragma unroll
    for (int i = 0; i < 8; i++) {
        float4 v0 = make_float4(acc[i][0], acc[i][1], acc[i][2], acc[i][3]);
        float4 v1 = make_float4(acc[i][4], acc[i][5], acc[i][6], acc[i][7]);
        float* row = &Out[(m0 + ty * 8 + i) * DFF + n0 + tx * 8];
        *(float4*)row       = v0;
        *(float4*)(row + 4) = v1;
    }
}

// ---------------------------------------------------------------------------
// Kernel 2: causal flash attention.
//   out[q,b,:] = softmax_k<=q( Q[q,b]·K[k,b] / 16 ) · V[k,b]
// BQ=32 queries per block, BKT=64 keys per tile, D=256.
// 256 threads: thread t handles query q=(t&31), dim chunk c=(t>>5) of 32 dims.
// Row stats computed redundantly per thread (no cross-warp reductions).
// qb order reversed so the heaviest causal blocks launch first.
// ---------------------------------------------------------------------------
#define BQ  32
#define BKT 64
#define TSTR 260   // K/V/Q tile row stride (floats): 16B-aligned, conflict-free
#define SSTR 65    // score tile row stride (odd -> conflict-free scalar access)

__global__ __launch_bounds__(256, 1) void flash_kernel(float* __restrict__ Outp)
{
    extern __shared__ float sm[];
    float* Qs  = sm;                       // [BQ ][TSTR]
    float* Ks  = Qs + BQ  * TSTR;          // [BKT][TSTR]
    float* Vs  = Ks + BKT * TSTR;          // [BKT][TSTR]
    float* Ssh = Vs + BKT * TSTR;          // [BQ ][SSTR]

    const int t  = threadIdx.x;
    const int q  = t & 31;
    const int c  = t >> 5;                 // 0..7
    const int qb = (gridDim.x - 1) - blockIdx.x;
    const int b  = blockIdx.y;
    const int q0 = qb * BQ;
    const int qg = q0 + q;

    // Load Q tile [BQ][256]
#pragma unroll
    for (int i = 0; i < 8; i++) {
        int f   = t + 256 * i;
        int row = f >> 6;
        int c4  = f & 63;
        *(float4*)&Qs[row * TSTR + c4 * 4] =
            *(const float4*)&Qg[((q0 + row) * BATCH + b) * DFF + c4 * 4];
    }

    float m = -INFINITY;
    float l = 0.f;
    float4 o[8];
#pragma unroll
    for (int i = 0; i < 8; i++) o[i] = make_float4(0.f, 0.f, 0.f, 0.f);

    const int n_kt = ((q0 + BQ - 1) >> 6) + 1;

    for (int kt = 0; kt < n_kt; kt++) {
        const int k0 = kt * BKT;

        __syncthreads();   // smem reuse barrier (also orders Qs stores on kt=0)
#pragma unroll
        for (int i = 0; i < 16; i++) {
            int f   = t + 256 * i;
            int row = f >> 6;
            int c4  = f & 63;
            int gofs = ((k0 + row) * BATCH + b) * DFF + c4 * 4;
            *(float4*)&Ks[row * TSTR + c4 * 4] = *(const float4*)&Kg[gofs];
            *(float4*)&Vs[row * TSTR + c4 * 4] = *(const float4*)&Vg[gofs];
        }
        __syncthreads();

        // ---- scores: this thread computes S[q][k0 + c*8 + j], j=0..7 ----
        float s[8];
#pragma unroll
        for (int j = 0; j < 8; j++) s[j] = 0.f;

        const float4* Qr = (const float4*)&Qs[q * TSTR];
#pragma unroll 4
        for (int d4 = 0; d4 < 64; d4++) {
            float4 qv = Qr[d4];
#pragma unroll
            for (int j = 0; j < 8; j++) {
                float4 kv = *(const float4*)&Ks[(c * 8 + j) * TSTR + d4 * 4];
                s[j] += qv.x * kv.x + qv.y * kv.y + qv.z * kv.z + qv.w * kv.w;
            }
        }
#pragma unroll
        for (int j = 0; j < 8; j++) {
            int   kgl = k0 + c * 8 + j;
            float val = s[j] * 0.0625f;           // 1/sqrt(256)
            if (kgl > qg) val = -1e30f;           // causal mask
            Ssh[q * SSTR + c * 8 + j] = val;
        }
        __syncthreads();

        // ---- online softmax stats (redundant per thread, conflict-free) ----
        float mt = -1e30f;
#pragma unroll 8
        for (int k = 0; k < BKT; k++) mt = fmaxf(mt, Ssh[q * SSTR + k]);
        float m_new = fmaxf(m, mt);
        float alpha = __expf(m - m_new);
        l *= alpha;
#pragma unroll
        for (int i = 0; i < 8; i++) {
            o[i].x *= alpha; o[i].y *= alpha; o[i].z *= alpha; o[i].w *= alpha;
        }

        // ---- P·V accumulate into registers ----
#pragma unroll 4
        for (int k = 0; k < BKT; k++) {
            float p = __expf(Ssh[q * SSTR + k] - m_new);
            l += p;
            const float4* Vr = (const float4*)&Vs[k * TSTR + c * 32];
#pragma unroll
            for (int d4 = 0; d4 < 8; d4++) {
                float4 v = Vr[d4];
                o[d4].x += p * v.x; o[d4].y += p * v.y;
                o[d4].z += p * v.z; o[d4].w += p * v.w;
            }
        }
        m = m_new;
    }

    const float inv = 1.f / l;
    float* orow = &Outp[(qg * BATCH + b) * DFF + c * 32];
#pragma unroll
    for (int d4 = 0; d4 < 8; d4++) {
        o[d4].x *= inv; o[d4].y *= inv; o[d4].z *= inv; o[d4].w *= inv;
        *(float4*)&orow[d4 * 4] = o[d4];
    }
}

// ---------------------------------------------------------------------------
// Launch. Inputs (metadata order): x, mask, W_q, W_k, W_v. mask is ignored
// (causal mask applied analytically; exp(-1e9+s-m) underflows to 0 in fp32,
// identical to the reference softmax result).
// ---------------------------------------------------------------------------
extern "C" void kernel_launch(void* const* d_in, const int* in_sizes, int n_in,
                              void* d_out, int out_size)
{
    const float* x  = (const float*)d_in[0];
    const float* Wq = (const float*)d_in[2];
    const float* Wk = (const float*)d_in[3];
    const float* Wv = (const float*)d_in[4];
    float* out = (float*)d_out;

    dim3 g1(M_ROWS / BM, DFF / BN, 3);
    proj_kernel<<<g1, 256>>>(x, Wq, Wk, Wv);

    const int smem = (BQ * TSTR + 2 * BKT * TSTR + BQ * SSTR) * (int)sizeof(float);
    cudaFuncSetAttribute(flash_kernel,
                         cudaFuncAttributeMaxDynamicSharedMemorySize, smem);
    dim3 g2(S_LEN / BQ, BATCH);
    flash_kernel<<<g2, 256, smem>>>(out);
}

// round 2
// speedup vs baseline: 1.3628x; 1.3628x over previous
#include <cuda_runtime.h>
#include <math.h>

#define S_LEN   4096
#define BATCH   2
#define DMODEL  1024
#define DFF     256
#define M_ROWS  (S_LEN * BATCH)   // 8192

typedef unsigned long long ull;

// Scratch
__device__ float Qg[M_ROWS * DFF];
__device__ float Kg[M_ROWS * DFF];
__device__ float Vg[M_ROWS * DFF];
// Split-K partials: [b][qb][chunk][row][256], m/l: [b][qb][chunk][row]
__device__ float OPart[2 * 64 * 4 * 64 * 256];
__device__ float MPart[2 * 64 * 4 * 64];
__device__ float LPart[2 * 64 * 4 * 64];

// ---------------- packed f32x2 helpers ----------------
__device__ __forceinline__ void fma2(ull &acc, ull a, ull b) {
    asm("fma.rn.f32x2 %0, %1, %2, %0;" : "+l"(acc) : "l"(a), "l"(b));
}
__device__ __forceinline__ ull mul2(ull a, ull b) {
    ull r; asm("mul.rn.f32x2 %0, %1, %2;" : "=l"(r) : "l"(a), "l"(b)); return r;
}
__device__ __forceinline__ ull pack2(float x) {
    ull r; asm("mov.b64 %0, {%1, %1};" : "=l"(r) : "f"(x)); return r;
}
__device__ __forceinline__ float2 unpack2(ull v) {
    float2 f; asm("mov.b64 {%0, %1}, %2;" : "=f"(f.x), "=f"(f.y) : "l"(v)); return f;
}

// ---------------------------------------------------------------------------
// Kernel 1: QKV projection (unchanged from R1 — 287us, ~62% of FMA peak).
// ---------------------------------------------------------------------------
#define BM 128
#define BN 128
#define BK 16

__global__ __launch_bounds__(256) void proj_kernel(
    const float* __restrict__ X,
    const float* __restrict__ Wq,
    const float* __restrict__ Wk,
    const float* __restrict__ Wv)
{
    __shared__ float As[BK][BM + 4];
    __shared__ float Bs[BK][BN + 4];

    const float* W;
    float* Out;
    if (blockIdx.z == 0)      { W = Wq; Out = Qg; }
    else if (blockIdx.z == 1) { W = Wk; Out = Kg; }
    else                      { W = Wv; Out = Vg; }

    const int t  = threadIdx.x;
    const int m0 = blockIdx.x * BM;
    const int n0 = blockIdx.y * BN;

    int arow[2], ac[2], brow[2], bc[2];
#pragma unroll
    for (int i = 0; i < 2; i++) {
        int f = t + 256 * i;
        arow[i] = f >> 2;  ac[i] = (f & 3) * 4;
        brow[i] = f >> 5;  bc[i] = (f & 31) * 4;
    }

    float4 pa[2], pb[2];
#pragma unroll
    for (int i = 0; i < 2; i++) {
        pa[i] = *(const float4*)&X[(m0 + arow[i]) * DMODEL + ac[i]];
        pb[i] = *(const float4*)&W[brow[i] * DFF + n0 + bc[i]];
    }

    float acc[8][8];
#pragma unroll
    for (int i = 0; i < 8; i++)
#pragma unroll
        for (int j = 0; j < 8; j++) acc[i][j] = 0.f;

    const int ty = t >> 4;
    const int tx = t & 15;

    const int NKT = DMODEL / BK;
    for (int kt = 0; kt < NKT; kt++) {
#pragma unroll
        for (int i = 0; i < 2; i++) {
            As[ac[i] + 0][arow[i]] = pa[i].x;
            As[ac[i] + 1][arow[i]] = pa[i].y;
            As[ac[i] + 2][arow[i]] = pa[i].z;
            As[ac[i] + 3][arow[i]] = pa[i].w;
            *(float4*)&Bs[brow[i]][bc[i]] = pb[i];
        }
        __syncthreads();

        if (kt + 1 < NKT) {
            int k0 = (kt + 1) * BK;
#pragma unroll
            for (int i = 0; i < 2; i++) {
                pa[i] = *(const float4*)&X[(m0 + arow[i]) * DMODEL + k0 + ac[i]];
                pb[i] = *(const float4*)&W[(k0 + brow[i]) * DFF + n0 + bc[i]];
            }
        }

#pragma unroll
        for (int kk = 0; kk < BK; kk++) {
            float4 a0 = *(const float4*)&As[kk][ty * 8];
            float4 a1 = *(const float4*)&As[kk][ty * 8 + 4];
            float4 b0 = *(const float4*)&Bs[kk][tx * 8];
            float4 b1 = *(const float4*)&Bs[kk][tx * 8 + 4];
            float a[8] = {a0.x, a0.y, a0.z, a0.w, a1.x, a1.y, a1.z, a1.w};
            float b[8] = {b0.x, b0.y, b0.z, b0.w, b1.x, b1.y, b1.z, b1.w};
#pragma unroll
            for (int i = 0; i < 8; i++)
#pragma unroll
                for (int j = 0; j < 8; j++)
                    acc[i][j] += a[i] * b[j];
        }
        __syncthreads();
    }

#pragma unroll
    for (int i = 0; i < 8; i++) {
        float4 v0 = make_float4(acc[i][0], acc[i][1], acc[i][2], acc[i][3]);
        float4 v1 = make_float4(acc[i][4], acc[i][5], acc[i][6], acc[i][7]);
        float* row = &Out[(m0 + ty * 8 + i) * DFF + n0 + tx * 8];
        *(float4*)row       = v0;
        *(float4*)(row + 4) = v1;
    }
}

// ---------------------------------------------------------------------------
// Kernel 2: causal flash attention, split-K chunks, register-blocked GEMMs.
//   BQ=64 queries/block, BKT=64 keys/tile, CHUNK=16 tiles per CTA.
//   256 threads: tq = t&15 (S d-frag q-rows / PV d-chunk), tk = t>>4.
//   S-role:  thread (tq,tk) computes S rows {tq+16i}, cols {tk+16j} (4x4).
//   PV-role: thread owns O rows {tk+16i}, d elements {4tq + 64cc} (4x16).
//   Partial-softmax output (unnormalized O, m, l) -> combine kernel.
// ---------------------------------------------------------------------------
#define BQ    64
#define BKT   64
#define TSTR  260
#define PSTR  68
#define MSTR  17
#define CHUNK 16

__global__ __launch_bounds__(256, 1) void flash2_kernel()
{
    extern __shared__ float sm[];
    float* Qs  = sm;                     // [64][260]
    float* Ks  = Qs + 64 * TSTR;         // [64][260]
    float* Vs  = Ks + 64 * TSTR;         // [64][260]
    float* Psh = Vs + 64 * TSTR;         // [64][68]
    float* Msh = Psh + 64 * PSTR;        // [64][17]

    const int t = threadIdx.x;
    const int b = blockIdx.y;

    // map linear chunk id -> (qb, c); reversed so long chunks launch first
    const int n = 159 - blockIdx.x;
    int qb, c;
    if (n < 16)      { qb = n;                  c = 0; }
    else if (n < 48) { int m_ = n - 16; qb = 16 + (m_ >> 1); c = m_ & 1; }
    else if (n < 96) { int m_ = n - 48; qb = 32 + m_ / 3;    c = m_ % 3; }
    else             { int m_ = n - 96; qb = 48 + (m_ >> 2); c = m_ & 3; }

    const int q0  = qb * BQ;
    const int kt0 = c * CHUNK;
    const int kt1 = min(kt0 + CHUNK, qb + 1);

    const int tq = t & 15;
    const int tk = t >> 4;

    // Load Q tile [64][256] once
#pragma unroll
    for (int i = 0; i < 16; i++) {
        int f = t + 256 * i;
        int row = f >> 6, c4 = f & 63;
        *(float4*)&Qs[row * TSTR + c4 * 4] =
            *(const float4*)&Qg[((q0 + row) * BATCH + b) * DFF + c4 * 4];
    }

    float m_s[4], m_p[4], l_p[4];
    ull   o[4][4][2];
#pragma unroll
    for (int i = 0; i < 4; i++) {
        m_s[i] = -INFINITY; m_p[i] = -INFINITY; l_p[i] = 0.f;
#pragma unroll
        for (int cc = 0; cc < 4; cc++) { o[i][cc][0] = 0ull; o[i][cc][1] = 0ull; }
    }

    for (int kt = kt0; kt < kt1; kt++) {
        __syncthreads();   // prev PV reads done; also orders Qs stores (kt0)

        // load K,V tiles
#pragma unroll
        for (int i = 0; i < 16; i++) {
            int f = t + 256 * i;
            int row = f >> 6, c4 = f & 63;
            int g = ((kt * 64 + row) * BATCH + b) * DFF + c4 * 4;
            *(float4*)&Ks[row * TSTR + c4 * 4] = *(const float4*)&Kg[g];
            *(float4*)&Vs[row * TSTR + c4 * 4] = *(const float4*)&Vg[g];
        }
        __syncthreads();

        // ---- S = Q K^T : 4x4 per-thread tile, f32x2 d-pair accumulation ----
        ull acc[4][4];
#pragma unroll
        for (int i = 0; i < 4; i++)
#pragma unroll
            for (int j = 0; j < 4; j++) acc[i][j] = 0ull;

#pragma unroll 4
        for (int d4 = 0; d4 < 64; d4++) {
            float4 qf[4], kf[4];
#pragma unroll
            for (int i = 0; i < 4; i++)
                qf[i] = *(const float4*)&Qs[(tq + 16 * i) * TSTR + d4 * 4];
#pragma unroll
            for (int j = 0; j < 4; j++)
                kf[j] = *(const float4*)&Ks[(tk + 16 * j) * TSTR + d4 * 4];
#pragma unroll
            for (int i = 0; i < 4; i++)
#pragma unroll
                for (int j = 0; j < 4; j++) {
                    fma2(acc[i][j], *(const ull*)&qf[i].x, *(const ull*)&kf[j].x);
                    fma2(acc[i][j], *(const ull*)&qf[i].z, *(const ull*)&kf[j].z);
                }
        }

        // mask + scale + per-thread partial row max -> Msh
        float sv[4][4];
#pragma unroll
        for (int i = 0; i < 4; i++) {
            float pm = -1e30f;
            int qg = q0 + tq + 16 * i;
#pragma unroll
            for (int j = 0; j < 4; j++) {
                float2 u = unpack2(acc[i][j]);
                float s = (u.x + u.y) * 0.0625f;       // 1/sqrt(256)
                if (kt * 64 + tk + 16 * j > qg) s = -1e30f;
                sv[i][j] = s;
                pm = fmaxf(pm, s);
            }
            Msh[(tq + 16 * i) * MSTR + tk] = pm;
        }
        __syncthreads();

        // S-role: row max -> exp -> Psh
#pragma unroll
        for (int i = 0; i < 4; i++) {
            int r = tq + 16 * i;
            float mt = -1e30f;
#pragma unroll
            for (int j16 = 0; j16 < 16; j16++) mt = fmaxf(mt, Msh[r * MSTR + j16]);
            float m_new = fmaxf(m_s[i], mt);
            m_s[i] = m_new;
#pragma unroll
            for (int j = 0; j < 4; j++)
                Psh[r * PSTR + tk + 16 * j] = __expf(sv[i][j] - m_new);
        }

        // PV-role: compute alpha for owned rows, rescale O/l
#pragma unroll
        for (int i = 0; i < 4; i++) {
            int r = tk + 16 * i;
            float mt = -1e30f;
#pragma unroll
            for (int j16 = 0; j16 < 16; j16++) mt = fmaxf(mt, Msh[r * MSTR + j16]);
            float m_new = fmaxf(m_p[i], mt);
            float alpha = __expf(m_p[i] - m_new);
            m_p[i] = m_new;
            l_p[i] *= alpha;
            ull a2 = pack2(alpha);
#pragma unroll
            for (int cc = 0; cc < 4; cc++) {
                o[i][cc][0] = mul2(o[i][cc][0], a2);
                o[i][cc][1] = mul2(o[i][cc][1], a2);
            }
        }
        __syncthreads();   // Psh ready

        // ---- O += P V : 4 rows x 16 d per thread ----
#pragma unroll 2
        for (int k = 0; k < BKT; k++) {
            float4 vf[4];
#pragma unroll
            for (int cc = 0; cc < 4; cc++)
                vf[cc] = *(const float4*)&Vs[k * TSTR + 4 * tq + 64 * cc];
#pragma unroll
            for (int i = 0; i < 4; i++) {
                float p = Psh[(tk + 16 * i) * PSTR + k];
                l_p[i] += p;
                ull pp = pack2(p);
#pragma unroll
                for (int cc = 0; cc < 4; cc++) {
                    fma2(o[i][cc][0], pp, *(const ull*)&vf[cc].x);
                    fma2(o[i][cc][1], pp, *(const ull*)&vf[cc].z);
                }
            }
        }
    }

    // write partials (unnormalized)
    const int base = ((b * 64 + qb) * 4 + c) * 64;
#pragma unroll
    for (int i = 0; i < 4; i++) {
        int r = tk + 16 * i;
        float* orow = &OPart[(base + r) * 256 + 4 * tq];
#pragma unroll
        for (int cc = 0; cc < 4; cc++) {
            float2 u0 = unpack2(o[i][cc][0]);
            float2 u1 = unpack2(o[i][cc][1]);
            *(float4*)&orow[64 * cc] = make_float4(u0.x, u0.y, u1.x, u1.y);
        }
        if (tq == 0) { MPart[base + r] = m_p[i]; LPart[base + r] = l_p[i]; }
    }
}

// ---------------------------------------------------------------------------
// Kernel 3: combine split-K partials with softmax renormalization.
// ---------------------------------------------------------------------------
__global__ __launch_bounds__(256) void combine_kernel(float* __restrict__ out)
{
    const int t = threadIdx.x;
    const int R = blockIdx.x * 4 + (t >> 6);   // 0..8191 = q*2+b
    const int q = R >> 1, b = R & 1;
    const int qb = q >> 6, r = q & 63;
    const int nc = (qb >> 4) + 1;
    const int mbase = ((b * 64 + qb) * 4) * 64 + r;

    float mx = -INFINITY;
    for (int cc = 0; cc < nc; cc++) mx = fmaxf(mx, MPart[mbase + cc * 64]);

    float w[4];
    float denom = 0.f;
    for (int cc = 0; cc < nc; cc++) {
        w[cc] = __expf(MPart[mbase + cc * 64] - mx);
        denom += w[cc] * LPart[mbase + cc * 64];
    }
    const float inv = 1.f / denom;

    const int d = (t & 63) * 4;
    float4 acc = make_float4(0.f, 0.f, 0.f, 0.f);
    for (int cc = 0; cc < nc; cc++) {
        const float4 v = *(const float4*)
            &OPart[(((b * 64 + qb) * 4 + cc) * 64 + r) * 256 + d];
        acc.x += w[cc] * v.x; acc.y += w[cc] * v.y;
        acc.z += w[cc] * v.z; acc.w += w[cc] * v.w;
    }
    acc.x *= inv; acc.y *= inv; acc.z *= inv; acc.w *= inv;
    *(float4*)&out[(q * BATCH + b) * DFF + d] = acc;
}

// ---------------------------------------------------------------------------
// Launch. Inputs: x, mask (ignored — causal applied analytically), W_q, W_k, W_v.
// ---------------------------------------------------------------------------
extern "C" void kernel_launch(void* const* d_in, const int* in_sizes, int n_in,
                              void* d_out, int out_size)
{
    const float* x  = (const float*)d_in[0];
    const float* Wq = (const float*)d_in[2];
    const float* Wk = (const float*)d_in[3];
    const float* Wv = (const float*)d_in[4];
    float* out = (float*)d_out;

    dim3 g1(M_ROWS / BM, DFF / BN, 3);
    proj_kernel<<<g1, 256>>>(x, Wq, Wk, Wv);

    const int smem = (3 * 64 * TSTR + 64 * PSTR + 64 * MSTR) * (int)sizeof(float);
    cudaFuncSetAttribute(flash2_kernel,
                         cudaFuncAttributeMaxDynamicSharedMemorySize, smem);
    dim3 g2(160, 2);
    flash2_kernel<<<g2, 256, smem>>>();

    combine_kernel<<<2048, 256>>>(out);
}

// round 4
// speedup vs baseline: 3.0545x; 2.2414x over previous
#include <cuda_runtime.h>
#include <cuda_bf16.h>
#include <math.h>
#include <stdint.h>

typedef __nv_bfloat16 bf16;
typedef unsigned int uint32;

// ============================ scratch =================================
__device__ bf16  Xh[8192 * 1024], Xl[8192 * 1024];
__device__ bf16  Wth[3 * 256 * 1024], Wtl[3 * 256 * 1024];   // W^T [proj][n][k]
__device__ bf16  Qh[2 * 4096 * 256], Ql[2 * 4096 * 256];
__device__ bf16  Kh[2 * 4096 * 256], Kl[2 * 4096 * 256];
__device__ bf16  Vh[2 * 4096 * 256], Vl[2 * 4096 * 256];
__device__ bf16  Vth[2 * 256 * 4096], Vtl[2 * 256 * 4096];   // V^T [b][d][s]
__device__ float Sg[2ull * 4096 * 4096];                     // raw scores fp32
__device__ bf16  Ph[2ull * 4096 * 4096], Pl[2ull * 4096 * 4096];
__device__ float OPart[2 * 32 * 4 * 128 * 256];              // PV split-K partials

// ============================ helpers =================================
__device__ __forceinline__ void split2(float x, bf16& h, bf16& l) {
    h = __float2bfloat16(x);
    l = __float2bfloat16(x - __bfloat162float(h));
}
__device__ __forceinline__ uint32 pk(bf16 a, bf16 b) {
    __nv_bfloat162 v(a, b);
    return *(uint32*)&v;
}
__device__ __forceinline__ void mma_bf16(float c[4], const uint32 a[4],
                                         const uint32 b[2]) {
    asm volatile(
        "mma.sync.aligned.m16n8k16.row.col.f32.bf16.bf16.f32 "
        "{%0,%1,%2,%3}, {%4,%5,%6,%7}, {%8,%9}, {%0,%1,%2,%3};"
        : "+f"(c[0]), "+f"(c[1]), "+f"(c[2]), "+f"(c[3])
        : "r"(a[0]), "r"(a[1]), "r"(a[2]), "r"(a[3]), "r"(b[0]), "r"(b[1]));
}

// ======================================================================
// Shared GEMM core: C[128 x 128] += A[128 x 64k-chunks] * B^T
// A, B stored K-major (row-major [row][k]), split hi/lo bf16 planes.
// 8 warps 2x4, warp tile 64x32, 3-pass split-bf16, fp32 accum in regs.
// Smem planes: 128 rows x 72 bf16 (stride 72 -> conflict-free frags).
// ======================================================================
#define RS   72
#define PL   18432                 // 128*72*2 bytes per plane
#define SMEM_GEMM (4 * PL)         // 73728

__device__ __forceinline__ void gemm128(
    const bf16* __restrict__ Agh, const bf16* __restrict__ Agl, size_t sA,
    const bf16* __restrict__ Bgh, const bf16* __restrict__ Bgl, size_t sB,
    int nchunk, char* smem, float acc[16][4])
{
    bf16* sAh = (bf16*)(smem);
    bf16* sAl = (bf16*)(smem + PL);
    bf16* sBh = (bf16*)(smem + 2 * PL);
    bf16* sBl = (bf16*)(smem + 3 * PL);
    const int t = threadIdx.x;
    const int wid = t >> 5, lane = t & 31;
    const int wm = wid >> 2, wn = wid & 3;
    const int gr = lane >> 2, tc = lane & 3;

    int row[4], c8[4];
#pragma unroll
    for (int i = 0; i < 4; i++) { int u = t + 256 * i; row[i] = u >> 3; c8[i] = u & 7; }

    float4 p0[4], p1[4], p2[4], p3[4];
#define GLOAD(k0) {                                                            \
    _Pragma("unroll") for (int i_ = 0; i_ < 4; i_++) {                         \
        p0[i_] = *(const float4*)(Agh + (size_t)row[i_] * sA + (k0) + c8[i_] * 8); \
        p1[i_] = *(const float4*)(Agl + (size_t)row[i_] * sA + (k0) + c8[i_] * 8); \
        p2[i_] = *(const float4*)(Bgh + (size_t)row[i_] * sB + (k0) + c8[i_] * 8); \
        p3[i_] = *(const float4*)(Bgl + (size_t)row[i_] * sB + (k0) + c8[i_] * 8); \
    } }

    GLOAD(0);
    for (int ch = 0; ch < nchunk; ch++) {
        __syncthreads();
#pragma unroll
        for (int i = 0; i < 4; i++) {
            int off = row[i] * RS + c8[i] * 8;
            *(float4*)(sAh + off) = p0[i];
            *(float4*)(sAl + off) = p1[i];
            *(float4*)(sBh + off) = p2[i];
            *(float4*)(sBl + off) = p3[i];
        }
        __syncthreads();
        if (ch + 1 < nchunk) GLOAD((ch + 1) * 64);

#pragma unroll
        for (int ks = 0; ks < 4; ks++) {
            uint32 ah[4][4], al[4][4], bh[4][2], bl[4][2];
#pragma unroll
            for (int mf = 0; mf < 4; mf++) {
                int o = (wm * 64 + mf * 16 + gr) * RS + ks * 16 + 2 * tc;
                ah[mf][0] = *(const uint32*)(sAh + o);
                ah[mf][1] = *(const uint32*)(sAh + o + 8 * RS);
                ah[mf][2] = *(const uint32*)(sAh + o + 8);
                ah[mf][3] = *(const uint32*)(sAh + o + 8 * RS + 8);
                al[mf][0] = *(const uint32*)(sAl + o);
                al[mf][1] = *(const uint32*)(sAl + o + 8 * RS);
                al[mf][2] = *(const uint32*)(sAl + o + 8);
                al[mf][3] = *(const uint32*)(sAl + o + 8 * RS + 8);
            }
#pragma unroll
            for (int nf = 0; nf < 4; nf++) {
                int o = (wn * 32 + nf * 8 + gr) * RS + ks * 16 + 2 * tc;
                bh[nf][0] = *(const uint32*)(sBh + o);
                bh[nf][1] = *(const uint32*)(sBh + o + 8);
                bl[nf][0] = *(const uint32*)(sBl + o);
                bl[nf][1] = *(const uint32*)(sBl + o + 8);
            }
#pragma unroll
            for (int mf = 0; mf < 4; mf++)
#pragma unroll
                for (int nf = 0; nf < 4; nf++) {
                    mma_bf16(acc[mf * 4 + nf], ah[mf], bh[nf]);
                    mma_bf16(acc[mf * 4 + nf], ah[mf], bl[nf]);
                    mma_bf16(acc[mf * 4 + nf], al[mf], bh[nf]);
                }
        }
    }
#undef GLOAD
}

// ============================ kernel 1: convert X =====================
__global__ __launch_bounds__(256) void cvt_x(const float* __restrict__ X) {
    const int N4 = 8192 * 1024 / 4;
    for (int i = blockIdx.x * 256 + threadIdx.x; i < N4; i += 2048 * 256) {
        float4 x = ((const float4*)X)[i];
        bf16 h0, l0, h1, l1, h2, l2, h3, l3;
        split2(x.x, h0, l0); split2(x.y, h1, l1);
        split2(x.z, h2, l2); split2(x.w, h3, l3);
        ((uint2*)Xh)[i] = make_uint2(pk(h0, h1), pk(h2, h3));
        ((uint2*)Xl)[i] = make_uint2(pk(l0, l1), pk(l2, l3));
    }
}

// ============================ kernel 2: convert+transpose W ===========
__global__ void cvt_w(const float* __restrict__ Wq, const float* __restrict__ Wk,
                      const float* __restrict__ Wv) {
    __shared__ float tile[32][33];
    const int pj = blockIdx.z;
    const float* W = (pj == 0) ? Wq : (pj == 1) ? Wk : Wv;
    const int k0 = blockIdx.x * 32, n0 = blockIdx.y * 32;
    const int tx = threadIdx.x, ty = threadIdx.y;
#pragma unroll
    for (int i = 0; i < 4; i++)
        tile[ty + 8 * i][tx] = W[(k0 + ty + 8 * i) * 256 + n0 + tx];
    __syncthreads();
#pragma unroll
    for (int i = 0; i < 4; i++) {
        int n = n0 + ty + 8 * i;
        bf16 h, l;
        split2(tile[tx][ty + 8 * i], h, l);
        Wth[pj * 262144 + n * 1024 + k0 + tx] = h;
        Wtl[pj * 262144 + n * 1024 + k0 + tx] = l;
    }
}

// ============================ kernel 3: projection GEMM ===============
__global__ __launch_bounds__(256) void proj_mma() {
    extern __shared__ char smem[];
    const int m0 = (blockIdx.x >> 1) * 128;
    const int nb = blockIdx.x & 1;
    const int pj = blockIdx.y;

    float acc[16][4];
#pragma unroll
    for (int i = 0; i < 16; i++)
#pragma unroll
        for (int j = 0; j < 4; j++) acc[i][j] = 0.f;

    gemm128(Xh + (size_t)m0 * 1024, Xl + (size_t)m0 * 1024, 1024,
            Wth + pj * 262144 + (size_t)(nb * 128) * 1024,
            Wtl + pj * 262144 + (size_t)(nb * 128) * 1024, 1024,
            16, smem, acc);

    bf16 *dh, *dl;
    if (pj == 0)      { dh = Qh; dl = Ql; }
    else if (pj == 1) { dh = Kh; dl = Kl; }
    else              { dh = Vh; dl = Vl; }

    const int t = threadIdx.x, wid = t >> 5, lane = t & 31;
    const int wm = wid >> 2, wn = wid & 3;
    const int gr = lane >> 2, tc = lane & 3;
#pragma unroll
    for (int mf = 0; mf < 4; mf++)
#pragma unroll
        for (int nf = 0; nf < 4; nf++)
#pragma unroll
            for (int h = 0; h < 2; h++) {
                int m = m0 + wm * 64 + mf * 16 + gr + 8 * h;
                int n = nb * 128 + wn * 32 + nf * 8 + 2 * tc;
                int s = m >> 1, b = m & 1;
                float v0 = acc[mf * 4 + nf][2 * h];
                float v1 = acc[mf * 4 + nf][2 * h + 1];
                bf16 h0, l0, h1, l1;
                split2(v0, h0, l0); split2(v1, h1, l1);
                size_t o = ((size_t)b * 4096 + s) * 256 + n;
                *(uint32*)(dh + o) = pk(h0, h1);
                *(uint32*)(dl + o) = pk(l0, l1);
            }
}

// ============================ kernel 4: V transpose ===================
__global__ __launch_bounds__(256) void vtrans() {
    __shared__ bf16 tile[64][80];
    const int t = threadIdx.x;
    const int s0 = blockIdx.x * 64, d0 = blockIdx.y * 64;
    const int b = blockIdx.z >> 1, plane = blockIdx.z & 1;
    const bf16* src = plane ? Vl : Vh;
    bf16* dst = plane ? Vtl : Vth;
#pragma unroll
    for (int i = 0; i < 2; i++) {
        int u = t + 256 * i, row = u >> 3, c8 = u & 7;
        float4 x = *(const float4*)(src + ((size_t)b * 4096 + s0 + row) * 256 + d0 + c8 * 8);
        *(float4*)&tile[row][c8 * 8] = x;
    }
    __syncthreads();
#pragma unroll
    for (int i = 0; i < 2; i++) {
        int u = t + 256 * i, d = u >> 3, g8 = u & 7;
        bf16 tmp[8];
#pragma unroll
        for (int j = 0; j < 8; j++) tmp[j] = tile[g8 * 8 + j][d];
        *(float4*)(dst + ((size_t)b * 256 + d0 + d) * 4096 + s0 + g8 * 8) = *(float4*)tmp;
    }
}

// ============================ kernel 5: S = Q K^T =====================
__global__ __launch_bounds__(256) void s_mma() {
    extern __shared__ char smem[];
    const int b = blockIdx.y;
    int n = 527 - blockIdx.x, qi = 0;           // reversed: big tiles first
    while (true) { int cnt = qi + 1; if (n < cnt) break; n -= cnt; qi++; }
    const int kb = n;

    float acc[16][4];
#pragma unroll
    for (int i = 0; i < 16; i++)
#pragma unroll
        for (int j = 0; j < 4; j++) acc[i][j] = 0.f;

    gemm128(Qh + ((size_t)b * 4096 + qi * 128) * 256,
            Ql + ((size_t)b * 4096 + qi * 128) * 256, 256,
            Kh + ((size_t)b * 4096 + kb * 128) * 256,
            Kl + ((size_t)b * 4096 + kb * 128) * 256, 256,
            4, smem, acc);

    const int t = threadIdx.x, wid = t >> 5, lane = t & 31;
    const int wm = wid >> 2, wn = wid & 3;
    const int gr = lane >> 2, tc = lane & 3;
#pragma unroll
    for (int mf = 0; mf < 4; mf++)
#pragma unroll
        for (int nf = 0; nf < 4; nf++)
#pragma unroll
            for (int h = 0; h < 2; h++) {
                int q = qi * 128 + wm * 64 + mf * 16 + gr + 8 * h;
                int k = kb * 128 + wn * 32 + nf * 8 + 2 * tc;
                float2 v = make_float2(acc[mf * 4 + nf][2 * h],
                                       acc[mf * 4 + nf][2 * h + 1]);
                *(float2*)(Sg + ((size_t)b * 4096 + q) * 4096 + k) = v;
            }
}

// ============================ kernel 6: softmax rows ==================
__global__ __launch_bounds__(128) void softmax_k() {
    __shared__ float red[4];
    const int t = threadIdx.x;
    const int b = blockIdx.x >> 12, q = blockIdx.x & 4095;
    const float* srow = Sg + ((size_t)b * 4096 + q) * 4096;
    const int len = q + 1;
    const int kend = ((q >> 7) + 1) << 7;
    const int nval4 = (len + 3) >> 2;

    float4 v[8];
    float mx = -1e30f;
#pragma unroll
    for (int it = 0; it < 8; it++) {
        int i4 = t + 128 * it;
        if (i4 < nval4) {
            float4 x = *(const float4*)(srow + i4 * 4);
            int k = i4 * 4;
            float a0 = (k + 0 < len) ? x.x * 0.0625f : -1e30f;
            float a1 = (k + 1 < len) ? x.y * 0.0625f : -1e30f;
            float a2 = (k + 2 < len) ? x.z * 0.0625f : -1e30f;
            float a3 = (k + 3 < len) ? x.w * 0.0625f : -1e30f;
            v[it] = make_float4(a0, a1, a2, a3);
            mx = fmaxf(mx, fmaxf(fmaxf(a0, a1), fmaxf(a2, a3)));
        } else {
            v[it] = make_float4(-1e30f, -1e30f, -1e30f, -1e30f);
        }
    }
#pragma unroll
    for (int o = 16; o; o >>= 1) mx = fmaxf(mx, __shfl_xor_sync(~0u, mx, o));
    if ((t & 31) == 0) red[t >> 5] = mx;
    __syncthreads();
    mx = fmaxf(fmaxf(red[0], red[1]), fmaxf(red[2], red[3]));
    __syncthreads();

    float sum = 0.f;
#pragma unroll
    for (int it = 0; it < 8; it++) {
        float4 p;
        p.x = __expf(v[it].x - mx); p.y = __expf(v[it].y - mx);
        p.z = __expf(v[it].z - mx); p.w = __expf(v[it].w - mx);
        v[it] = p;
        if (t + 128 * it < nval4) sum += p.x + p.y + p.z + p.w;
    }
#pragma unroll
    for (int o = 16; o; o >>= 1) sum += __shfl_xor_sync(~0u, sum, o);
    if ((t & 31) == 0) red[t >> 5] = sum;
    __syncthreads();
    sum = red[0] + red[1] + red[2] + red[3];
    const float inv = 1.f / sum;

    bf16* ph = Ph + ((size_t)b * 4096 + q) * 4096;
    bf16* pl = Pl + ((size_t)b * 4096 + q) * 4096;
#pragma unroll
    for (int it = 0; it < 8; it++) {
        int i4 = t + 128 * it;
        if (i4 * 4 < kend) {
            float p0 = 0, p1 = 0, p2 = 0, p3 = 0;
            if (i4 < nval4) {
                p0 = v[it].x * inv; p1 = v[it].y * inv;
                p2 = v[it].z * inv; p3 = v[it].w * inv;
            }
            bf16 h0, l0, h1, l1, h2, l2, h3, l3;
            split2(p0, h0, l0); split2(p1, h1, l1);
            split2(p2, h2, l2); split2(p3, h3, l3);
            *(uint2*)(ph + i4 * 4) = make_uint2(pk(h0, h1), pk(h2, h3));
            *(uint2*)(pl + i4 * 4) = make_uint2(pk(l0, l1), pk(l2, l3));
        }
    }
}

// ============================ kernel 7: O = P V =======================
__global__ __launch_bounds__(256) void pv_mma() {
    extern __shared__ char smem[];
    const int b = blockIdx.y;
    const int nb = blockIdx.x & 1;
    int n = 79 - (blockIdx.x >> 1), qi = 0;     // reversed
    while (true) { int cnt = (qi >> 3) + 1; if (n < cnt) break; n -= cnt; qi++; }
    const int c = n;
    const int kst = c * 1024;
    const int ken = min(kst + 1024, qi * 128 + 128);
    const int NC = (ken - kst) >> 6;

    float acc[16][4];
#pragma unroll
    for (int i = 0; i < 16; i++)
#pragma unroll
        for (int j = 0; j < 4; j++) acc[i][j] = 0.f;

    gemm128(Ph + ((size_t)b * 4096 + qi * 128) * 4096 + kst,
            Pl + ((size_t)b * 4096 + qi * 128) * 4096 + kst, 4096,
            Vth + ((size_t)b * 256 + nb * 128) * 4096 + kst,
            Vtl + ((size_t)b * 256 + nb * 128) * 4096 + kst, 4096,
            NC, smem, acc);

    const int t = threadIdx.x, wid = t >> 5, lane = t & 31;
    const int wm = wid >> 2, wn = wid & 3;
    const int gr = lane >> 2, tc = lane & 3;
    float* base = OPart + (((size_t)(b * 32 + qi) * 4 + c) * 128) * 256;
#pragma unroll
    for (int mf = 0; mf < 4; mf++)
#pragma unroll
        for (int nf = 0; nf < 4; nf++)
#pragma unroll
            for (int h = 0; h < 2; h++) {
                int r = wm * 64 + mf * 16 + gr + 8 * h;
                int d = nb * 128 + wn * 32 + nf * 8 + 2 * tc;
                float2 v = make_float2(acc[mf * 4 + nf][2 * h],
                                       acc[mf * 4 + nf][2 * h + 1]);
                *(float2*)(base + (size_t)r * 256 + d) = v;
            }
}

// ============================ kernel 8: combine =======================
__global__ __launch_bounds__(256) void combine_k(float* __restrict__ out) {
    const int t = threadIdx.x;
    const int R = blockIdx.x * 4 + (t >> 6);   // = q*2 + b
    const int q = R >> 1, b = R & 1;
    const int qi = q >> 7, r = q & 127;
    const int nc = (qi >> 3) + 1;
    const int d = (t & 63) * 4;

    float4 acc = make_float4(0.f, 0.f, 0.f, 0.f);
    for (int c = 0; c < nc; c++) {
        const float4 v = *(const float4*)
            (OPart + (((size_t)(b * 32 + qi) * 4 + c) * 128 + r) * 256 + d);
        acc.x += v.x; acc.y += v.y; acc.z += v.z; acc.w += v.w;
    }
    *(float4*)(out + (size_t)R * 256 + d) = acc;
}

// ============================ launch ==================================
extern "C" void kernel_launch(void* const* d_in, const int* in_sizes, int n_in,
                              void* d_out, int out_size) {
    const float* x  = (const float*)d_in[0];
    const float* Wq = (const float*)d_in[2];
    const float* Wk = (const float*)d_in[3];
    const float* Wv = (const float*)d_in[4];
    float* out = (float*)d_out;

    cudaFuncSetAttribute(proj_mma, cudaFuncAttributeMaxDynamicSharedMemorySize, SMEM_GEMM);
    cudaFuncSetAttribute(s_mma,    cudaFuncAttributeMaxDynamicSharedMemorySize, SMEM_GEMM);
    cudaFuncSetAttribute(pv_mma,   cudaFuncAttributeMaxDynamicSharedMemorySize, SMEM_GEMM);

    cvt_x<<<2048, 256>>>(x);
    cvt_w<<<dim3(32, 8, 3), dim3(32, 8)>>>(Wq, Wk, Wv);
    proj_mma<<<dim3(128, 3), 256, SMEM_GEMM>>>();
    vtrans<<<dim3(64, 4, 4), 256>>>();
    s_mma<<<dim3(528, 2), 256, SMEM_GEMM>>>();
    softmax_k<<<8192, 128>>>();
    pv_mma<<<dim3(160, 2), 256, SMEM_GEMM>>>();
    combine_k<<<2048, 256>>>(out);
}

// round 5
// speedup vs baseline: 3.0863x; 1.0104x over previous
#include <cuda_runtime.h>
#include <cuda_bf16.h>
#include <math.h>
#include <stdint.h>

typedef __nv_bfloat16 bf16;
typedef unsigned int uint32;

// ============================ scratch =================================
__device__ bf16  Xh[8192 * 1024], Xl[8192 * 1024];
__device__ bf16  Wth[3 * 256 * 1024], Wtl[3 * 256 * 1024];   // W^T [proj][n][k]
__device__ bf16  Qh[2 * 4096 * 256], Ql[2 * 4096 * 256];
__device__ bf16  Kh[2 * 4096 * 256], Kl[2 * 4096 * 256];
__device__ bf16  Vh[2 * 4096 * 256], Vl[2 * 4096 * 256];
__device__ bf16  Vth[2 * 256 * 4096], Vtl[2 * 256 * 4096];   // V^T [b][d][s]
__device__ float OPart[2ull * 64 * 8 * 64 * 256];            // split-K partials
__device__ float MPart[2 * 64 * 8 * 64];
__device__ float LPart[2 * 64 * 8 * 64];

// ============================ helpers =================================
__device__ __forceinline__ void split2(float x, bf16& h, bf16& l) {
    h = __float2bfloat16(x);
    l = __float2bfloat16(x - __bfloat162float(h));
}
__device__ __forceinline__ uint32 pk(bf16 a, bf16 b) {
    __nv_bfloat162 v(a, b);
    return *(uint32*)&v;
}
__device__ __forceinline__ void mma_bf16(float c[4], const uint32 a[4],
                                         const uint32 b[2]) {
    asm volatile(
        "mma.sync.aligned.m16n8k16.row.col.f32.bf16.bf16.f32 "
        "{%0,%1,%2,%3}, {%4,%5,%6,%7}, {%8,%9}, {%0,%1,%2,%3};"
        : "+f"(c[0]), "+f"(c[1]), "+f"(c[2]), "+f"(c[3])
        : "r"(a[0]), "r"(a[1]), "r"(a[2]), "r"(a[3]), "r"(b[0]), "r"(b[1]));
}

// ======================================================================
// GEMM core for projections (unchanged from R4 — passing, ~70us).
// ======================================================================
#define RS   72
#define PL   18432
#define SMEM_GEMM (4 * PL)

__device__ __forceinline__ void gemm128(
    const bf16* __restrict__ Agh, const bf16* __restrict__ Agl, size_t sA,
    const bf16* __restrict__ Bgh, const bf16* __restrict__ Bgl, size_t sB,
    int nchunk, char* smem, float acc[16][4])
{
    bf16* sAh = (bf16*)(smem);
    bf16* sAl = (bf16*)(smem + PL);
    bf16* sBh = (bf16*)(smem + 2 * PL);
    bf16* sBl = (bf16*)(smem + 3 * PL);
    const int t = threadIdx.x;
    const int wid = t >> 5, lane = t & 31;
    const int wm = wid >> 2, wn = wid & 3;
    const int gr = lane >> 2, tc = lane & 3;

    int row[4], c8[4];
#pragma unroll
    for (int i = 0; i < 4; i++) { int u = t + 256 * i; row[i] = u >> 3; c8[i] = u & 7; }

    float4 p0[4], p1[4], p2[4], p3[4];
#define GLOAD(k0) {                                                            \
    _Pragma("unroll") for (int i_ = 0; i_ < 4; i_++) {                         \
        p0[i_] = *(const float4*)(Agh + (size_t)row[i_] * sA + (k0) + c8[i_] * 8); \
        p1[i_] = *(const float4*)(Agl + (size_t)row[i_] * sA + (k0) + c8[i_] * 8); \
        p2[i_] = *(const float4*)(Bgh + (size_t)row[i_] * sB + (k0) + c8[i_] * 8); \
        p3[i_] = *(const float4*)(Bgl + (size_t)row[i_] * sB + (k0) + c8[i_] * 8); \
    } }

    GLOAD(0);
    for (int ch = 0; ch < nchunk; ch++) {
        __syncthreads();
#pragma unroll
        for (int i = 0; i < 4; i++) {
            int off = row[i] * RS + c8[i] * 8;
            *(float4*)(sAh + off) = p0[i];
            *(float4*)(sAl + off) = p1[i];
            *(float4*)(sBh + off) = p2[i];
            *(float4*)(sBl + off) = p3[i];
        }
        __syncthreads();
        if (ch + 1 < nchunk) GLOAD((ch + 1) * 64);

#pragma unroll
        for (int ks = 0; ks < 4; ks++) {
            uint32 ah[4][4], al[4][4], bh[4][2], bl[4][2];
#pragma unroll
            for (int mf = 0; mf < 4; mf++) {
                int o = (wm * 64 + mf * 16 + gr) * RS + ks * 16 + 2 * tc;
                ah[mf][0] = *(const uint32*)(sAh + o);
                ah[mf][1] = *(const uint32*)(sAh + o + 8 * RS);
                ah[mf][2] = *(const uint32*)(sAh + o + 8);
                ah[mf][3] = *(const uint32*)(sAh + o + 8 * RS + 8);
                al[mf][0] = *(const uint32*)(sAl + o);
                al[mf][1] = *(const uint32*)(sAl + o + 8 * RS);
                al[mf][2] = *(const uint32*)(sAl + o + 8);
                al[mf][3] = *(const uint32*)(sAl + o + 8 * RS + 8);
            }
#pragma unroll
            for (int nf = 0; nf < 4; nf++) {
                int o = (wn * 32 + nf * 8 + gr) * RS + ks * 16 + 2 * tc;
                bh[nf][0] = *(const uint32*)(sBh + o);
                bh[nf][1] = *(const uint32*)(sBh + o + 8);
                bl[nf][0] = *(const uint32*)(sBl + o);
                bl[nf][1] = *(const uint32*)(sBl + o + 8);
            }
#pragma unroll
            for (int mf = 0; mf < 4; mf++)
#pragma unroll
                for (int nf = 0; nf < 4; nf++) {
                    mma_bf16(acc[mf * 4 + nf], ah[mf], bh[nf]);
                    mma_bf16(acc[mf * 4 + nf], ah[mf], bl[nf]);
                    mma_bf16(acc[mf * 4 + nf], al[mf], bh[nf]);
                }
        }
    }
#undef GLOAD
}

// ============================ kernel 1: convert X =====================
__global__ __launch_bounds__(256) void cvt_x(const float* __restrict__ X) {
    const int N4 = 8192 * 1024 / 4;
    for (int i = blockIdx.x * 256 + threadIdx.x; i < N4; i += 2048 * 256) {
        float4 x = ((const float4*)X)[i];
        bf16 h0, l0, h1, l1, h2, l2, h3, l3;
        split2(x.x, h0, l0); split2(x.y, h1, l1);
        split2(x.z, h2, l2); split2(x.w, h3, l3);
        ((uint2*)Xh)[i] = make_uint2(pk(h0, h1), pk(h2, h3));
        ((uint2*)Xl)[i] = make_uint2(pk(l0, l1), pk(l2, l3));
    }
}

// ============================ kernel 2: convert+transpose W ===========
__global__ void cvt_w(const float* __restrict__ Wq, const float* __restrict__ Wk,
                      const float* __restrict__ Wv) {
    __shared__ float tile[32][33];
    const int pj = blockIdx.z;
    const float* W = (pj == 0) ? Wq : (pj == 1) ? Wk : Wv;
    const int k0 = blockIdx.x * 32, n0 = blockIdx.y * 32;
    const int tx = threadIdx.x, ty = threadIdx.y;
#pragma unroll
    for (int i = 0; i < 4; i++)
        tile[ty + 8 * i][tx] = W[(k0 + ty + 8 * i) * 256 + n0 + tx];
    __syncthreads();
#pragma unroll
    for (int i = 0; i < 4; i++) {
        int n = n0 + ty + 8 * i;
        bf16 h, l;
        split2(tile[tx][ty + 8 * i], h, l);
        Wth[pj * 262144 + n * 1024 + k0 + tx] = h;
        Wtl[pj * 262144 + n * 1024 + k0 + tx] = l;
    }
}

// ============================ kernel 3: projection GEMM ===============
__global__ __launch_bounds__(256) void proj_mma() {
    extern __shared__ char smem[];
    const int m0 = (blockIdx.x >> 1) * 128;
    const int nb = blockIdx.x & 1;
    const int pj = blockIdx.y;

    float acc[16][4];
#pragma unroll
    for (int i = 0; i < 16; i++)
#pragma unroll
        for (int j = 0; j < 4; j++) acc[i][j] = 0.f;

    gemm128(Xh + (size_t)m0 * 1024, Xl + (size_t)m0 * 1024, 1024,
            Wth + pj * 262144 + (size_t)(nb * 128) * 1024,
            Wtl + pj * 262144 + (size_t)(nb * 128) * 1024, 1024,
            16, smem, acc);

    bf16 *dh, *dl;
    if (pj == 0)      { dh = Qh; dl = Ql; }
    else if (pj == 1) { dh = Kh; dl = Kl; }
    else              { dh = Vh; dl = Vl; }

    const int t = threadIdx.x, wid = t >> 5, lane = t & 31;
    const int wm = wid >> 2, wn = wid & 3;
    const int gr = lane >> 2, tc = lane & 3;
#pragma unroll
    for (int mf = 0; mf < 4; mf++)
#pragma unroll
        for (int nf = 0; nf < 4; nf++)
#pragma unroll
            for (int h = 0; h < 2; h++) {
                int m = m0 + wm * 64 + mf * 16 + gr + 8 * h;
                int n = nb * 128 + wn * 32 + nf * 8 + 2 * tc;
                int s = m >> 1, b = m & 1;
                float v0 = acc[mf * 4 + nf][2 * h];
                float v1 = acc[mf * 4 + nf][2 * h + 1];
                bf16 h0, l0, h1, l1;
                split2(v0, h0, l0); split2(v1, h1, l1);
                size_t o = ((size_t)b * 4096 + s) * 256 + n;
                *(uint32*)(dh + o) = pk(h0, h1);
                *(uint32*)(dl + o) = pk(l0, l1);
            }
}

// ============================ kernel 4: V transpose ===================
__global__ __launch_bounds__(256) void vtrans() {
    __shared__ bf16 tile[64][80];
    const int t = threadIdx.x;
    const int s0 = blockIdx.x * 64, d0 = blockIdx.y * 64;
    const int b = blockIdx.z >> 1, plane = blockIdx.z & 1;
    const bf16* src = plane ? Vl : Vh;
    bf16* dst = plane ? Vtl : Vth;
#pragma unroll
    for (int i = 0; i < 2; i++) {
        int u = t + 256 * i, row = u >> 3, c8 = u & 7;
        float4 x = *(const float4*)(src + ((size_t)b * 4096 + s0 + row) * 256 + d0 + c8 * 8);
        *(float4*)&tile[row][c8 * 8] = x;
    }
    __syncthreads();
#pragma unroll
    for (int i = 0; i < 2; i++) {
        int u = t + 256 * i, d = u >> 3, g8 = u & 7;
        bf16 tmp[8];
#pragma unroll
        for (int j = 0; j < 8; j++) tmp[j] = tile[g8 * 8 + j][d];
        *(float4*)(dst + ((size_t)b * 256 + d0 + d) * 4096 + s0 + g8 * 8) = *(float4*)tmp;
    }
}

// ======================================================================
// Kernel 5: fused flash attention (S = QK^T -> online softmax -> O = PV)
// CTA: 64-query tile, split-K chunk of 4 key-tiles (512 keys).
// 8 warps 2x4: S warp-tile 32x32, O warp-tile 32x64. bf16 3-pass split.
// Outputs unnormalized O + (m, l) per row per chunk -> combine kernel.
// ======================================================================
// smem byte offsets (regions reused between S and PV phases)
#define F_QH 0
#define F_QL 9216
#define F_KH 18432
#define F_KL 36864          // S phase end: 55296
#define F_VH 0
#define F_VL 36864          // PV phase end: 73728
#define F_PH 73728
#define F_PL 91136          // P planes end: 108544
#define F_MX 108544         // 64 x 4 floats
#define F_SZ 109568

__global__ __launch_bounds__(256) void fa_mma() {
    extern __shared__ char sm[];
    const int t = threadIdx.x, wid = t >> 5, lane = t & 31;
    const int wm = wid >> 2, wn = wid & 3;
    const int gr = lane >> 2, tc = lane & 3;
    const int b = blockIdx.y;

    // chunk decode (reversed: biggest qi first)
    int n = 287 - blockIdx.x;
    int g = 1, base = 0;
    while (n >= base + 8 * g) { base += 8 * g; g++; }
    const int idx = n - base;
    const int qi = (g - 1) * 8 + idx / g;
    const int c  = idx % g;
    const int kt_diag = qi >> 1;
    const int kt0 = c * 4;
    const int kt1 = min(kt0 + 4, kt_diag + 1);
    const int q0 = qi * 64;

    float acc_o[2][8][4];
#pragma unroll
    for (int mf = 0; mf < 2; mf++)
#pragma unroll
        for (int nf = 0; nf < 8; nf++)
#pragma unroll
            for (int ci = 0; ci < 4; ci++) acc_o[mf][nf][ci] = 0.f;
    float m[4] = {-INFINITY, -INFINITY, -INFINITY, -INFINITY};
    float l[4] = {0.f, 0.f, 0.f, 0.f};

    const uint32* qh32 = (const uint32*)(sm + F_QH);
    const uint32* ql32 = (const uint32*)(sm + F_QL);
    const uint32* kh32 = (const uint32*)(sm + F_KH);
    const uint32* kl32 = (const uint32*)(sm + F_KL);
    const uint32* vh32 = (const uint32*)(sm + F_VH);
    const uint32* vl32 = (const uint32*)(sm + F_VL);
    uint32* ph32 = (uint32*)(sm + F_PH);
    uint32* pl32 = (uint32*)(sm + F_PL);
    float* pmax = (float*)(sm + F_MX);

    for (int kt = kt0; kt < kt1; kt++) {
        const bool diag = (kt == kt_diag);

        // ---------------- S = Q K^T over 4 d-chunks ----------------
        float acc_s[2][4][4];
#pragma unroll
        for (int mf = 0; mf < 2; mf++)
#pragma unroll
            for (int nf = 0; nf < 4; nf++)
#pragma unroll
                for (int ci = 0; ci < 4; ci++) acc_s[mf][nf][ci] = 0.f;

        for (int dc = 0; dc < 4; dc++) {
            const int d0 = dc * 64;
            float4 rq[2][2], rk[2][4];
#pragma unroll
            for (int i = 0; i < 2; i++) {
                int u = t + 256 * i, r = u >> 3, c8 = u & 7;
                size_t go = ((size_t)(b * 4096 + q0 + r)) * 256 + d0 + c8 * 8;
                rq[0][i] = *(const float4*)(Qh + go);
                rq[1][i] = *(const float4*)(Ql + go);
            }
#pragma unroll
            for (int i = 0; i < 4; i++) {
                int u = t + 256 * i, r = u >> 3, c8 = u & 7;
                size_t go = ((size_t)(b * 4096 + kt * 128 + r)) * 256 + d0 + c8 * 8;
                rk[0][i] = *(const float4*)(Kh + go);
                rk[1][i] = *(const float4*)(Kl + go);
            }
            __syncthreads();   // previous readers of this smem done
#pragma unroll
            for (int i = 0; i < 2; i++) {
                int u = t + 256 * i, r = u >> 3, c8 = u & 7;
                int off = r * 144 + c8 * 16;
                *(float4*)(sm + F_QH + off) = rq[0][i];
                *(float4*)(sm + F_QL + off) = rq[1][i];
            }
#pragma unroll
            for (int i = 0; i < 4; i++) {
                int u = t + 256 * i, r = u >> 3, c8 = u & 7;
                int off = r * 144 + c8 * 16;
                *(float4*)(sm + F_KH + off) = rk[0][i];
                *(float4*)(sm + F_KL + off) = rk[1][i];
            }
            __syncthreads();

#pragma unroll
            for (int ks = 0; ks < 4; ks++) {
                uint32 ah[2][4], al[2][4], bh[4][2], bl[4][2];
#pragma unroll
                for (int mf = 0; mf < 2; mf++) {
                    int o = (wm * 32 + mf * 16 + gr) * 36 + ks * 8 + tc;
                    ah[mf][0] = qh32[o];          ah[mf][1] = qh32[o + 8 * 36];
                    ah[mf][2] = qh32[o + 4];      ah[mf][3] = qh32[o + 8 * 36 + 4];
                    al[mf][0] = ql32[o];          al[mf][1] = ql32[o + 8 * 36];
                    al[mf][2] = ql32[o + 4];      al[mf][3] = ql32[o + 8 * 36 + 4];
                }
#pragma unroll
                for (int nf = 0; nf < 4; nf++) {
                    int o = (wn * 32 + nf * 8 + gr) * 36 + ks * 8 + tc;
                    bh[nf][0] = kh32[o];  bh[nf][1] = kh32[o + 4];
                    bl[nf][0] = kl32[o];  bl[nf][1] = kl32[o + 4];
                }
#pragma unroll
                for (int mf = 0; mf < 2; mf++)
#pragma unroll
                    for (int nf = 0; nf < 4; nf++) {
                        mma_bf16(acc_s[mf][nf], ah[mf], bh[nf]);
                        mma_bf16(acc_s[mf][nf], ah[mf], bl[nf]);
                        mma_bf16(acc_s[mf][nf], al[mf], bh[nf]);
                    }
            }
        }

        // ---------------- scale + mask + row-max ----------------
        float pm[4] = {-1e30f, -1e30f, -1e30f, -1e30f};
#pragma unroll
        for (int mf = 0; mf < 2; mf++)
#pragma unroll
            for (int nf = 0; nf < 4; nf++)
#pragma unroll
                for (int ci = 0; ci < 4; ci++) {
                    float s = acc_s[mf][nf][ci] * 0.0625f;
                    if (diag) {
                        int qg = q0 + wm * 32 + mf * 16 + gr + (ci >> 1) * 8;
                        int kg = kt * 128 + wn * 32 + nf * 8 + 2 * tc + (ci & 1);
                        if (kg > qg) s = -1e30f;
                    }
                    acc_s[mf][nf][ci] = s;
                    int ri = mf * 2 + (ci >> 1);
                    pm[ri] = fmaxf(pm[ri], s);
                }
#pragma unroll
        for (int i = 0; i < 4; i++) {
            pm[i] = fmaxf(pm[i], __shfl_xor_sync(~0u, pm[i], 1));
            pm[i] = fmaxf(pm[i], __shfl_xor_sync(~0u, pm[i], 2));
        }
        if (tc == 0) {
#pragma unroll
            for (int i = 0; i < 4; i++) {
                int row = wm * 32 + (i >> 1) * 16 + (i & 1) * 8 + gr;
                pmax[row * 4 + wn] = pm[i];
            }
        }
        __syncthreads();   // pmax visible; S-phase smem reads done

        float alpha[4];
#pragma unroll
        for (int i = 0; i < 4; i++) {
            int row = wm * 32 + (i >> 1) * 16 + (i & 1) * 8 + gr;
            float mt = fmaxf(fmaxf(pmax[row * 4 + 0], pmax[row * 4 + 1]),
                             fmaxf(pmax[row * 4 + 2], pmax[row * 4 + 3]));
            float m_new = fmaxf(m[i], mt);
            alpha[i] = __expf(m[i] - m_new);
            m[i] = m_new;
            l[i] *= alpha[i];
        }
#pragma unroll
        for (int mf = 0; mf < 2; mf++)
#pragma unroll
            for (int nf = 0; nf < 8; nf++)
#pragma unroll
                for (int ci = 0; ci < 4; ci++)
                    acc_o[mf][nf][ci] *= alpha[mf * 2 + (ci >> 1)];

        // ---------------- exp -> split P into smem ----------------
#pragma unroll
        for (int mf = 0; mf < 2; mf++)
#pragma unroll
            for (int nf = 0; nf < 4; nf++)
#pragma unroll
                for (int h = 0; h < 2; h++) {
                    int ri = mf * 2 + h;
                    float p0 = __expf(acc_s[mf][nf][h * 2 + 0] - m[ri]);
                    float p1 = __expf(acc_s[mf][nf][h * 2 + 1] - m[ri]);
                    l[ri] += p0 + p1;
                    bf16 h0, l0, h1, l1;
                    split2(p0, h0, l0); split2(p1, h1, l1);
                    int row = wm * 32 + mf * 16 + h * 8 + gr;
                    int o = row * 68 + wn * 16 + nf * 4 + tc;
                    ph32[o] = pk(h0, h1);
                    pl32[o] = pk(l0, l1);
                }

        // ---------------- PV over 2 key-chunks ----------------
#pragma unroll
        for (int kc = 0; kc < 2; kc++) {
            float4 rv[2][8];
#pragma unroll
            for (int i = 0; i < 8; i++) {
                int u = t + 256 * i, d = u >> 3, c8 = u & 7;
                size_t go = ((size_t)(b * 256 + d)) * 4096 + kt * 128 + kc * 64 + c8 * 8;
                rv[0][i] = *(const float4*)(Vth + go);
                rv[1][i] = *(const float4*)(Vtl + go);
            }
            if (kc == 0) {
                // pmax sync above already guarantees S-smem reads are done
            } else {
                __syncthreads();   // PV chunk0 reads done before overwrite
            }
            // for kc==0 the earlier __syncthreads covers ordering; for safety:
            if (kc == 0) __syncthreads();
#pragma unroll
            for (int i = 0; i < 8; i++) {
                int u = t + 256 * i, d = u >> 3, c8 = u & 7;
                int off = d * 144 + c8 * 16;
                *(float4*)(sm + F_VH + off) = rv[0][i];
                *(float4*)(sm + F_VL + off) = rv[1][i];
            }
            __syncthreads();

#pragma unroll
            for (int ks = 0; ks < 4; ks++) {
                uint32 ah[2][4], al[2][4], bh[8][2], bl[8][2];
#pragma unroll
                for (int mf = 0; mf < 2; mf++) {
                    int o = (wm * 32 + mf * 16 + gr) * 68 + kc * 32 + ks * 8 + tc;
                    ah[mf][0] = ph32[o];      ah[mf][1] = ph32[o + 8 * 68];
                    ah[mf][2] = ph32[o + 4];  ah[mf][3] = ph32[o + 8 * 68 + 4];
                    al[mf][0] = pl32[o];      al[mf][1] = pl32[o + 8 * 68];
                    al[mf][2] = pl32[o + 4];  al[mf][3] = pl32[o + 8 * 68 + 4];
                }
#pragma unroll
                for (int nf = 0; nf < 8; nf++) {
                    int o = (wn * 64 + nf * 8 + gr) * 36 + ks * 8 + tc;
                    bh[nf][0] = vh32[o];  bh[nf][1] = vh32[o + 4];
                    bl[nf][0] = vl32[o];  bl[nf][1] = vl32[o + 4];
                }
#pragma unroll
                for (int mf = 0; mf < 2; mf++)
#pragma unroll
                    for (int nf = 0; nf < 8; nf++) {
                        mma_bf16(acc_o[mf][nf], ah[mf], bh[nf]);
                        mma_bf16(acc_o[mf][nf], ah[mf], bl[nf]);
                        mma_bf16(acc_o[mf][nf], al[mf], bh[nf]);
                    }
            }
        }
        __syncthreads();   // PV reads done before next ktile's smem stores
    }

    // ---------------- epilogue: reduce l, write partials ----------------
#pragma unroll
    for (int i = 0; i < 4; i++) {
        l[i] += __shfl_xor_sync(~0u, l[i], 1);
        l[i] += __shfl_xor_sync(~0u, l[i], 2);
    }
    if (tc == 0) {
#pragma unroll
        for (int i = 0; i < 4; i++) {
            int row = wm * 32 + (i >> 1) * 16 + (i & 1) * 8 + gr;
            pmax[row * 4 + wn] = l[i];
        }
    }
    __syncthreads();

    const size_t pb = ((size_t)(b * 64 + qi) * 8 + c) * 64;
#pragma unroll
    for (int i = 0; i < 4; i++) {
        int row = wm * 32 + (i >> 1) * 16 + (i & 1) * 8 + gr;
        if (wn == 0 && tc == 0) {
            float lr = pmax[row * 4 + 0] + pmax[row * 4 + 1] +
                       pmax[row * 4 + 2] + pmax[row * 4 + 3];
            MPart[pb + row] = m[i];
            LPart[pb + row] = lr;
        }
    }
#pragma unroll
    for (int mf = 0; mf < 2; mf++)
#pragma unroll
        for (int h = 0; h < 2; h++) {
            int row = wm * 32 + mf * 16 + h * 8 + gr;
            float* orow = OPart + (pb + row) * 256;
#pragma unroll
            for (int nf = 0; nf < 8; nf++) {
                float2 v = make_float2(acc_o[mf][nf][h * 2 + 0],
                                       acc_o[mf][nf][h * 2 + 1]);
                *(float2*)(orow + wn * 64 + nf * 8 + 2 * tc) = v;
            }
        }
}

// ============================ kernel 6: combine =======================
__global__ __launch_bounds__(256) void combine_k(float* __restrict__ out) {
    const int t = threadIdx.x;
    const int R = blockIdx.x * 4 + (t >> 6);   // = q*2 + b
    const int q = R >> 1, b = R & 1;
    const int qi = q >> 6, r = q & 63;
    const int nc = (qi >> 3) + 1;
    const size_t cb = ((size_t)(b * 64 + qi) * 8) * 64 + r;

    float mx = -INFINITY;
    for (int c = 0; c < nc; c++) mx = fmaxf(mx, MPart[cb + (size_t)c * 64]);
    float w[8];
    float denom = 0.f;
    for (int c = 0; c < nc; c++) {
        w[c] = __expf(MPart[cb + (size_t)c * 64] - mx);
        denom += w[c] * LPart[cb + (size_t)c * 64];
    }
    const float inv = 1.f / denom;

    const int d = (t & 63) * 4;
    float4 acc = make_float4(0.f, 0.f, 0.f, 0.f);
    for (int c = 0; c < nc; c++) {
        const float4 v = *(const float4*)
            (OPart + (cb + (size_t)c * 64) * 256 + d);
        acc.x += w[c] * v.x; acc.y += w[c] * v.y;
        acc.z += w[c] * v.z; acc.w += w[c] * v.w;
    }
    acc.x *= inv; acc.y *= inv; acc.z *= inv; acc.w *= inv;
    *(float4*)(out + (size_t)R * 256 + d) = acc;
}

// ============================ launch ==================================
extern "C" void kernel_launch(void* const* d_in, const int* in_sizes, int n_in,
                              void* d_out, int out_size) {
    const float* x  = (const float*)d_in[0];
    const float* Wq = (const float*)d_in[2];
    const float* Wk = (const float*)d_in[3];
    const float* Wv = (const float*)d_in[4];
    float* out = (float*)d_out;

    cudaFuncSetAttribute(proj_mma, cudaFuncAttributeMaxDynamicSharedMemorySize, SMEM_GEMM);
    cudaFuncSetAttribute(fa_mma,   cudaFuncAttributeMaxDynamicSharedMemorySize, F_SZ);

    cvt_x<<<2048, 256>>>(x);
    cvt_w<<<dim3(32, 8, 3), dim3(32, 8)>>>(Wq, Wk, Wv);
    proj_mma<<<dim3(128, 3), 256, SMEM_GEMM>>>();
    vtrans<<<dim3(64, 4, 4), 256>>>();
    fa_mma<<<dim3(288, 2), 256, F_SZ>>>();
    combine_k<<<2048, 256>>>(out);
}

// round 6
// speedup vs baseline: 3.6296x; 1.1760x over previous
#include <cuda_runtime.h>
#include <cuda_fp16.h>
#include <math.h>
#include <stdint.h>

typedef __half f16;
typedef unsigned int uint32;

// ============================ scratch =================================
__device__ f16   Xh[8192 * 1024], Xl[8192 * 1024];
__device__ f16   Wth[3 * 256 * 1024], Wtl[3 * 256 * 1024];   // W^T [proj][n][k]
__device__ f16   Qh[2 * 4096 * 256], Ql[2 * 4096 * 256];
__device__ f16   Kh[2 * 4096 * 256];                         // hi plane only
__device__ f16   Vh[2 * 4096 * 256];                         // hi plane only
__device__ f16   Vth[2 * 256 * 4096];                        // V^T [b][d][s]
__device__ float OPart[2ull * 64 * 8 * 64 * 256];            // split-K partials
__device__ float MPart[2 * 64 * 8 * 64];
__device__ float LPart[2 * 64 * 8 * 64];

// ============================ helpers =================================
__device__ __forceinline__ void split2(float x, f16& h, f16& l) {
    h = __float2half(x);
    l = __float2half(x - __half2float(h));
}
__device__ __forceinline__ uint32 pk(f16 a, f16 b) {
    __half2 v(a, b);
    return *(uint32*)&v;
}
__device__ __forceinline__ void mma_f16(float c[4], const uint32 a[4],
                                        const uint32 b[2]) {
    asm volatile(
        "mma.sync.aligned.m16n8k16.row.col.f32.f16.f16.f32 "
        "{%0,%1,%2,%3}, {%4,%5,%6,%7}, {%8,%9}, {%0,%1,%2,%3};"
        : "+f"(c[0]), "+f"(c[1]), "+f"(c[2]), "+f"(c[3])
        : "r"(a[0]), "r"(a[1]), "r"(a[2]), "r"(a[3]), "r"(b[0]), "r"(b[1]));
}

// ======================================================================
// GEMM core for projections: 3-pass fp16 split (error ~2^-22).
// ======================================================================
#define RS   72
#define PL   18432
#define SMEM_GEMM (4 * PL)

__device__ __forceinline__ void gemm128(
    const f16* __restrict__ Agh, const f16* __restrict__ Agl, size_t sA,
    const f16* __restrict__ Bgh, const f16* __restrict__ Bgl, size_t sB,
    int nchunk, char* smem, float acc[16][4])
{
    f16* sAh = (f16*)(smem);
    f16* sAl = (f16*)(smem + PL);
    f16* sBh = (f16*)(smem + 2 * PL);
    f16* sBl = (f16*)(smem + 3 * PL);
    const int t = threadIdx.x;
    const int wid = t >> 5, lane = t & 31;
    const int wm = wid >> 2, wn = wid & 3;
    const int gr = lane >> 2, tc = lane & 3;

    int row[4], c8[4];
#pragma unroll
    for (int i = 0; i < 4; i++) { int u = t + 256 * i; row[i] = u >> 3; c8[i] = u & 7; }

    float4 p0[4], p1[4], p2[4], p3[4];
#define GLOAD(k0) {                                                            \
    _Pragma("unroll") for (int i_ = 0; i_ < 4; i_++) {                         \
        p0[i_] = *(const float4*)(Agh + (size_t)row[i_] * sA + (k0) + c8[i_] * 8); \
        p1[i_] = *(const float4*)(Agl + (size_t)row[i_] * sA + (k0) + c8[i_] * 8); \
        p2[i_] = *(const float4*)(Bgh + (size_t)row[i_] * sB + (k0) + c8[i_] * 8); \
        p3[i_] = *(const float4*)(Bgl + (size_t)row[i_] * sB + (k0) + c8[i_] * 8); \
    } }

    GLOAD(0);
    for (int ch = 0; ch < nchunk; ch++) {
        __syncthreads();
#pragma unroll
        for (int i = 0; i < 4; i++) {
            int off = row[i] * RS + c8[i] * 8;
            *(float4*)(sAh + off) = p0[i];
            *(float4*)(sAl + off) = p1[i];
            *(float4*)(sBh + off) = p2[i];
            *(float4*)(sBl + off) = p3[i];
        }
        __syncthreads();
        if (ch + 1 < nchunk) GLOAD((ch + 1) * 64);

#pragma unroll
        for (int ks = 0; ks < 4; ks++) {
            uint32 ah[4][4], al[4][4], bh[4][2], bl[4][2];
#pragma unroll
            for (int mf = 0; mf < 4; mf++) {
                int o = (wm * 64 + mf * 16 + gr) * RS + ks * 16 + 2 * tc;
                ah[mf][0] = *(const uint32*)(sAh + o);
                ah[mf][1] = *(const uint32*)(sAh + o + 8 * RS);
                ah[mf][2] = *(const uint32*)(sAh + o + 8);
                ah[mf][3] = *(const uint32*)(sAh + o + 8 * RS + 8);
                al[mf][0] = *(const uint32*)(sAl + o);
                al[mf][1] = *(const uint32*)(sAl + o + 8 * RS);
                al[mf][2] = *(const uint32*)(sAl + o + 8);
                al[mf][3] = *(const uint32*)(sAl + o + 8 * RS + 8);
            }
#pragma unroll
            for (int nf = 0; nf < 4; nf++) {
                int o = (wn * 32 + nf * 8 + gr) * RS + ks * 16 + 2 * tc;
                bh[nf][0] = *(const uint32*)(sBh + o);
                bh[nf][1] = *(const uint32*)(sBh + o + 8);
                bl[nf][0] = *(const uint32*)(sBl + o);
                bl[nf][1] = *(const uint32*)(sBl + o + 8);
            }
#pragma unroll
            for (int mf = 0; mf < 4; mf++)
#pragma unroll
                for (int nf = 0; nf < 4; nf++) {
                    mma_f16(acc[mf * 4 + nf], ah[mf], bh[nf]);
                    mma_f16(acc[mf * 4 + nf], ah[mf], bl[nf]);
                    mma_f16(acc[mf * 4 + nf], al[mf], bh[nf]);
                }
        }
    }
#undef GLOAD
}

// ============================ kernel 1: convert X =====================
__global__ __launch_bounds__(256) void cvt_x(const float* __restrict__ X) {
    const int N4 = 8192 * 1024 / 4;
    for (int i = blockIdx.x * 256 + threadIdx.x; i < N4; i += 2048 * 256) {
        float4 x = ((const float4*)X)[i];
        f16 h0, l0, h1, l1, h2, l2, h3, l3;
        split2(x.x, h0, l0); split2(x.y, h1, l1);
        split2(x.z, h2, l2); split2(x.w, h3, l3);
        ((uint2*)Xh)[i] = make_uint2(pk(h0, h1), pk(h2, h3));
        ((uint2*)Xl)[i] = make_uint2(pk(l0, l1), pk(l2, l3));
    }
}

// ============================ kernel 2: convert+transpose W ===========
__global__ void cvt_w(const float* __restrict__ Wq, const float* __restrict__ Wk,
                      const float* __restrict__ Wv) {
    __shared__ float tile[32][33];
    const int pj = blockIdx.z;
    const float* W = (pj == 0) ? Wq : (pj == 1) ? Wk : Wv;
    const int k0 = blockIdx.x * 32, n0 = blockIdx.y * 32;
    const int tx = threadIdx.x, ty = threadIdx.y;
#pragma unroll
    for (int i = 0; i < 4; i++)
        tile[ty + 8 * i][tx] = W[(k0 + ty + 8 * i) * 256 + n0 + tx];
    __syncthreads();
#pragma unroll
    for (int i = 0; i < 4; i++) {
        int n = n0 + ty + 8 * i;
        f16 h, l;
        split2(tile[tx][ty + 8 * i], h, l);
        Wth[pj * 262144 + n * 1024 + k0 + tx] = h;
        Wtl[pj * 262144 + n * 1024 + k0 + tx] = l;
    }
}

// ============================ kernel 3: projection GEMM ===============
__global__ __launch_bounds__(256) void proj_mma() {
    extern __shared__ char smem[];
    const int m0 = (blockIdx.x >> 1) * 128;
    const int nb = blockIdx.x & 1;
    const int pj = blockIdx.y;

    float acc[16][4];
#pragma unroll
    for (int i = 0; i < 16; i++)
#pragma unroll
        for (int j = 0; j < 4; j++) acc[i][j] = 0.f;

    gemm128(Xh + (size_t)m0 * 1024, Xl + (size_t)m0 * 1024, 1024,
            Wth + pj * 262144 + (size_t)(nb * 128) * 1024,
            Wtl + pj * 262144 + (size_t)(nb * 128) * 1024, 1024,
            16, smem, acc);

    f16* dh = (pj == 0) ? Qh : (pj == 1) ? Kh : Vh;
    const bool two = (pj == 0);   // only Q keeps its lo plane

    const int t = threadIdx.x, wid = t >> 5, lane = t & 31;
    const int wm = wid >> 2, wn = wid & 3;
    const int gr = lane >> 2, tc = lane & 3;
#pragma unroll
    for (int mf = 0; mf < 4; mf++)
#pragma unroll
        for (int nf = 0; nf < 4; nf++)
#pragma unroll
            for (int h = 0; h < 2; h++) {
                int m = m0 + wm * 64 + mf * 16 + gr + 8 * h;
                int n = nb * 128 + wn * 32 + nf * 8 + 2 * tc;
                int s = m >> 1, b = m & 1;
                float v0 = acc[mf * 4 + nf][2 * h];
                float v1 = acc[mf * 4 + nf][2 * h + 1];
                f16 h0, l0, h1, l1;
                split2(v0, h0, l0); split2(v1, h1, l1);
                size_t o = ((size_t)b * 4096 + s) * 256 + n;
                *(uint32*)(dh + o) = pk(h0, h1);
                if (two) *(uint32*)(Ql + o) = pk(l0, l1);
            }
}

// ============================ kernel 4: V transpose (hi only) =========
__global__ __launch_bounds__(256) void vtrans() {
    __shared__ f16 tile[64][80];
    const int t = threadIdx.x;
    const int s0 = blockIdx.x * 64, d0 = blockIdx.y * 64;
    const int b = blockIdx.z;
#pragma unroll
    for (int i = 0; i < 2; i++) {
        int u = t + 256 * i, row = u >> 3, c8 = u & 7;
        float4 x = *(const float4*)(Vh + ((size_t)b * 4096 + s0 + row) * 256 + d0 + c8 * 8);
        *(float4*)&tile[row][c8 * 8] = x;
    }
    __syncthreads();
#pragma unroll
    for (int i = 0; i < 2; i++) {
        int u = t + 256 * i, d = u >> 3, g8 = u & 7;
        f16 tmp[8];
#pragma unroll
        for (int j = 0; j < 8; j++) tmp[j] = tile[g8 * 8 + j][d];
        *(float4*)(Vth + ((size_t)b * 256 + d0 + d) * 4096 + s0 + g8 * 8) = *(float4*)tmp;
    }
}

// ======================================================================
// Kernel 5: fused flash attention, fp16 2-pass both stages.
//   S = (Qh+Ql)·Kh    (dropped: Q·Kresid ~ 2.4e-4 abs in scores)
//   O = (Ph+Pl)·Vh    (dropped: P·Vresid ~ 2.4e-4 rel)
// CTA: 64-query tile, split-K chunk of 4 key-tiles. 8 warps 2x4.
// ======================================================================
#define F_QH 0
#define F_QL 9216
#define F_KH 18432          // S phase region ends 36864
#define F_VH 0              // V overlays Q/K region (36864 bytes)
#define F_PH 36864
#define F_PL 54272          // P planes end 71680
#define F_MX 71680          // 64 x 4 floats
#define F_SZ 72704

__global__ __launch_bounds__(256) void fa_mma() {
    extern __shared__ char sm[];
    const int t = threadIdx.x, wid = t >> 5, lane = t & 31;
    const int wm = wid >> 2, wn = wid & 3;
    const int gr = lane >> 2, tc = lane & 3;
    const int b = blockIdx.y;

    // chunk decode (reversed: biggest qi first)
    int n = 287 - blockIdx.x;
    int g = 1, base = 0;
    while (n >= base + 8 * g) { base += 8 * g; g++; }
    const int idx = n - base;
    const int qi = (g - 1) * 8 + idx / g;
    const int c  = idx % g;
    const int kt_diag = qi >> 1;
    const int kt0 = c * 4;
    const int kt1 = min(kt0 + 4, kt_diag + 1);
    const int q0 = qi * 64;

    float acc_o[2][8][4];
#pragma unroll
    for (int mf = 0; mf < 2; mf++)
#pragma unroll
        for (int nf = 0; nf < 8; nf++)
#pragma unroll
            for (int ci = 0; ci < 4; ci++) acc_o[mf][nf][ci] = 0.f;
    float m[4] = {-INFINITY, -INFINITY, -INFINITY, -INFINITY};
    float l[4] = {0.f, 0.f, 0.f, 0.f};

    const uint32* qh32 = (const uint32*)(sm + F_QH);
    const uint32* ql32 = (const uint32*)(sm + F_QL);
    const uint32* kh32 = (const uint32*)(sm + F_KH);
    const uint32* vh32 = (const uint32*)(sm + F_VH);
    uint32* ph32 = (uint32*)(sm + F_PH);
    uint32* pl32 = (uint32*)(sm + F_PL);
    float* pmax = (float*)(sm + F_MX);

    for (int kt = kt0; kt < kt1; kt++) {
        const bool diag = (kt == kt_diag);

        // ---------------- S = Q K^T over 4 d-chunks ----------------
        float acc_s[2][4][4];
#pragma unroll
        for (int mf = 0; mf < 2; mf++)
#pragma unroll
            for (int nf = 0; nf < 4; nf++)
#pragma unroll
                for (int ci = 0; ci < 4; ci++) acc_s[mf][nf][ci] = 0.f;

        for (int dc = 0; dc < 4; dc++) {
            const int d0 = dc * 64;
            float4 rq[2][2], rk[4];
#pragma unroll
            for (int i = 0; i < 2; i++) {
                int u = t + 256 * i, r = u >> 3, c8 = u & 7;
                size_t go = ((size_t)(b * 4096 + q0 + r)) * 256 + d0 + c8 * 8;
                rq[0][i] = *(const float4*)(Qh + go);
                rq[1][i] = *(const float4*)(Ql + go);
            }
#pragma unroll
            for (int i = 0; i < 4; i++) {
                int u = t + 256 * i, r = u >> 3, c8 = u & 7;
                size_t go = ((size_t)(b * 4096 + kt * 128 + r)) * 256 + d0 + c8 * 8;
                rk[i] = *(const float4*)(Kh + go);
            }
            __syncthreads();   // previous readers of this smem done
#pragma unroll
            for (int i = 0; i < 2; i++) {
                int u = t + 256 * i, r = u >> 3, c8 = u & 7;
                int off = r * 144 + c8 * 16;
                *(float4*)(sm + F_QH + off) = rq[0][i];
                *(float4*)(sm + F_QL + off) = rq[1][i];
            }
#pragma unroll
            for (int i = 0; i < 4; i++) {
                int u = t + 256 * i, r = u >> 3, c8 = u & 7;
                *(float4*)(sm + F_KH + r * 144 + c8 * 16) = rk[i];
            }
            __syncthreads();

#pragma unroll
            for (int ks = 0; ks < 4; ks++) {
                uint32 ah[2][4], al[2][4], bh[4][2];
#pragma unroll
                for (int mf = 0; mf < 2; mf++) {
                    int o = (wm * 32 + mf * 16 + gr) * 36 + ks * 8 + tc;
                    ah[mf][0] = qh32[o];          ah[mf][1] = qh32[o + 8 * 36];
                    ah[mf][2] = qh32[o + 4];      ah[mf][3] = qh32[o + 8 * 36 + 4];
                    al[mf][0] = ql32[o];          al[mf][1] = ql32[o + 8 * 36];
                    al[mf][2] = ql32[o + 4];      al[mf][3] = ql32[o + 8 * 36 + 4];
                }
#pragma unroll
                for (int nf = 0; nf < 4; nf++) {
                    int o = (wn * 32 + nf * 8 + gr) * 36 + ks * 8 + tc;
                    bh[nf][0] = kh32[o];  bh[nf][1] = kh32[o + 4];
                }
#pragma unroll
                for (int mf = 0; mf < 2; mf++)
#pragma unroll
                    for (int nf = 0; nf < 4; nf++) {
                        mma_f16(acc_s[mf][nf], ah[mf], bh[nf]);
                        mma_f16(acc_s[mf][nf], al[mf], bh[nf]);
                    }
            }
        }

        // ---------------- scale + mask + row-max ----------------
        float pm[4] = {-1e30f, -1e30f, -1e30f, -1e30f};
#pragma unroll
        for (int mf = 0; mf < 2; mf++)
#pragma unroll
            for (int nf = 0; nf < 4; nf++)
#pragma unroll
                for (int ci = 0; ci < 4; ci++) {
                    float s = acc_s[mf][nf][ci] * 0.0625f;
                    if (diag) {
                        int qg = q0 + wm * 32 + mf * 16 + gr + (ci >> 1) * 8;
                        int kg = kt * 128 + wn * 32 + nf * 8 + 2 * tc + (ci & 1);
                        if (kg > qg) s = -1e30f;
                    }
                    acc_s[mf][nf][ci] = s;
                    int ri = mf * 2 + (ci >> 1);
                    pm[ri] = fmaxf(pm[ri], s);
                }
#pragma unroll
        for (int i = 0; i < 4; i++) {
            pm[i] = fmaxf(pm[i], __shfl_xor_sync(~0u, pm[i], 1));
            pm[i] = fmaxf(pm[i], __shfl_xor_sync(~0u, pm[i], 2));
        }
        if (tc == 0) {
#pragma unroll
            for (int i = 0; i < 4; i++) {
                int row = wm * 32 + (i >> 1) * 16 + (i & 1) * 8 + gr;
                pmax[row * 4 + wn] = pm[i];
            }
        }
        __syncthreads();   // pmax visible; S-phase smem reads done

        float alpha[4];
#pragma unroll
        for (int i = 0; i < 4; i++) {
            int row = wm * 32 + (i >> 1) * 16 + (i & 1) * 8 + gr;
            float mt = fmaxf(fmaxf(pmax[row * 4 + 0], pmax[row * 4 + 1]),
                             fmaxf(pmax[row * 4 + 2], pmax[row * 4 + 3]));
            float m_new = fmaxf(m[i], mt);
            alpha[i] = __expf(m[i] - m_new);
            m[i] = m_new;
            l[i] *= alpha[i];
        }
#pragma unroll
        for (int mf = 0; mf < 2; mf++)
#pragma unroll
            for (int nf = 0; nf < 8; nf++)
#pragma unroll
                for (int ci = 0; ci < 4; ci++)
                    acc_o[mf][nf][ci] *= alpha[mf * 2 + (ci >> 1)];

        // ---------------- exp -> split P into smem ----------------
#pragma unroll
        for (int mf = 0; mf < 2; mf++)
#pragma unroll
            for (int nf = 0; nf < 4; nf++)
#pragma unroll
                for (int h = 0; h < 2; h++) {
                    int ri = mf * 2 + h;
                    float p0 = __expf(acc_s[mf][nf][h * 2 + 0] - m[ri]);
                    float p1 = __expf(acc_s[mf][nf][h * 2 + 1] - m[ri]);
                    l[ri] += p0 + p1;
                    f16 h0, l0, h1, l1;
                    split2(p0, h0, l0); split2(p1, h1, l1);
                    int row = wm * 32 + mf * 16 + h * 8 + gr;
                    int o = row * 68 + wn * 16 + nf * 4 + tc;
                    ph32[o] = pk(h0, h1);
                    pl32[o] = pk(l0, l1);
                }

        // ---------------- PV over 2 key-chunks ----------------
#pragma unroll
        for (int kc = 0; kc < 2; kc++) {
            float4 rv[8];
#pragma unroll
            for (int i = 0; i < 8; i++) {
                int u = t + 256 * i, d = u >> 3, c8 = u & 7;
                size_t go = ((size_t)(b * 256 + d)) * 4096 + kt * 128 + kc * 64 + c8 * 8;
                rv[i] = *(const float4*)(Vth + go);
            }
            __syncthreads();   // prior readers of V region done
#pragma unroll
            for (int i = 0; i < 8; i++) {
                int u = t + 256 * i, d = u >> 3, c8 = u & 7;
                *(float4*)(sm + F_VH + d * 144 + c8 * 16) = rv[i];
            }
            __syncthreads();   // V + P visible

#pragma unroll
            for (int ks = 0; ks < 4; ks++) {
                uint32 ah[2][4], al[2][4], bh[8][2];
#pragma unroll
                for (int mf = 0; mf < 2; mf++) {
                    int o = (wm * 32 + mf * 16 + gr) * 68 + kc * 32 + ks * 8 + tc;
                    ah[mf][0] = ph32[o];      ah[mf][1] = ph32[o + 8 * 68];
                    ah[mf][2] = ph32[o + 4];  ah[mf][3] = ph32[o + 8 * 68 + 4];
                    al[mf][0] = pl32[o];      al[mf][1] = pl32[o + 8 * 68];
                    al[mf][2] = pl32[o + 4];  al[mf][3] = pl32[o + 8 * 68 + 4];
                }
#pragma unroll
                for (int nf = 0; nf < 8; nf++) {
                    int o = (wn * 64 + nf * 8 + gr) * 36 + ks * 8 + tc;
                    bh[nf][0] = vh32[o];  bh[nf][1] = vh32[o + 4];
                }
#pragma unroll
                for (int mf = 0; mf < 2; mf++)
#pragma unroll
                    for (int nf = 0; nf < 8; nf++) {
                        mma_f16(acc_o[mf][nf], ah[mf], bh[nf]);
                        mma_f16(acc_o[mf][nf], al[mf], bh[nf]);
                    }
            }
        }
        __syncthreads();   // PV reads done before next ktile's smem stores
    }

    // ---------------- epilogue: reduce l, write partials ----------------
#pragma unroll
    for (int i = 0; i < 4; i++) {
        l[i] += __shfl_xor_sync(~0u, l[i], 1);
        l[i] += __shfl_xor_sync(~0u, l[i], 2);
    }
    if (tc == 0) {
#pragma unroll
        for (int i = 0; i < 4; i++) {
            int row = wm * 32 + (i >> 1) * 16 + (i & 1) * 8 + gr;
            pmax[row * 4 + wn] = l[i];
        }
    }
    __syncthreads();

    const size_t pb = ((size_t)(b * 64 + qi) * 8 + c) * 64;
#pragma unroll
    for (int i = 0; i < 4; i++) {
        int row = wm * 32 + (i >> 1) * 16 + (i & 1) * 8 + gr;
        if (wn == 0 && tc == 0) {
            float lr = pmax[row * 4 + 0] + pmax[row * 4 + 1] +
                       pmax[row * 4 + 2] + pmax[row * 4 + 3];
            MPart[pb + row] = m[i];
            LPart[pb + row] = lr;
        }
    }
#pragma unroll
    for (int mf = 0; mf < 2; mf++)
#pragma unroll
        for (int h = 0; h < 2; h++) {
            int row = wm * 32 + mf * 16 + h * 8 + gr;
            float* orow = OPart + (pb + row) * 256;
#pragma unroll
            for (int nf = 0; nf < 8; nf++) {
                float2 v = make_float2(acc_o[mf][nf][h * 2 + 0],
                                       acc_o[mf][nf][h * 2 + 1]);
                *(float2*)(orow + wn * 64 + nf * 8 + 2 * tc) = v;
            }
        }
}

// ============================ kernel 6: combine =======================
__global__ __launch_bounds__(256) void combine_k(float* __restrict__ out) {
    const int t = threadIdx.x;
    const int R = blockIdx.x * 4 + (t >> 6);   // = q*2 + b
    const int q = R >> 1, b = R & 1;
    const int qi = q >> 6, r = q & 63;
    const int nc = (qi >> 3) + 1;
    const size_t cb = ((size_t)(b * 64 + qi) * 8) * 64 + r;

    float mx = -INFINITY;
    for (int c = 0; c < nc; c++) mx = fmaxf(mx, MPart[cb + (size_t)c * 64]);
    float w[8];
    float denom = 0.f;
    for (int c = 0; c < nc; c++) {
        w[c] = __expf(MPart[cb + (size_t)c * 64] - mx);
        denom += w[c] * LPart[cb + (size_t)c * 64];
    }
    const float inv = 1.f / denom;

    const int d = (t & 63) * 4;
    float4 acc = make_float4(0.f, 0.f, 0.f, 0.f);
    for (int c = 0; c < nc; c++) {
        const float4 v = *(const float4*)
            (OPart + (cb + (size_t)c * 64) * 256 + d);
        acc.x += w[c] * v.x; acc.y += w[c] * v.y;
        acc.z += w[c] * v.z; acc.w += w[c] * v.w;
    }
    acc.x *= inv; acc.y *= inv; acc.z *= inv; acc.w *= inv;
    *(float4*)(out + (size_t)R * 256 + d) = acc;
}

// ============================ launch ==================================
extern "C" void kernel_launch(void* const* d_in, const int* in_sizes, int n_in,
                              void* d_out, int out_size) {
    const float* x  = (const float*)d_in[0];
    const float* Wq = (const float*)d_in[2];
    const float* Wk = (const float*)d_in[3];
    const float* Wv = (const float*)d_in[4];
    float* out = (float*)d_out;

    cudaFuncSetAttribute(proj_mma, cudaFuncAttributeMaxDynamicSharedMemorySize, SMEM_GEMM);
    cudaFuncSetAttribute(fa_mma,   cudaFuncAttributeMaxDynamicSharedMemorySize, F_SZ);

    cvt_x<<<2048, 256>>>(x);
    cvt_w<<<dim3(32, 8, 3), dim3(32, 8)>>>(Wq, Wk, Wv);
    proj_mma<<<dim3(128, 3), 256, SMEM_GEMM>>>();
    vtrans<<<dim3(64, 4, 2), 256>>>();
    fa_mma<<<dim3(288, 2), 256, F_SZ>>>();
    combine_k<<<2048, 256>>>(out);
}

// round 8
// speedup vs baseline: 4.3486x; 1.1981x over previous
#include <cuda_runtime.h>
#include <cuda_fp16.h>
#include <math.h>
#include <stdint.h>

typedef __half f16;
typedef unsigned int uint32;

// ============================ scratch =================================
__device__ f16   Xh[8192 * 1024], Xl[8192 * 1024];
__device__ f16   Wth[3 * 256 * 1024], Wtl[3 * 256 * 1024];   // W^T [proj][n][k]
__device__ f16   Qh[2 * 4096 * 256];
__device__ f16   Kh[2 * 4096 * 256];
__device__ f16   Vh[2 * 4096 * 256];
__device__ f16   Vth[2 * 256 * 4096];                        // V^T [b][d][s]
__device__ float OPart[2ull * 64 * 4 * 64 * 256];            // split-K partials
__device__ float MPart[2 * 64 * 4 * 64];
__device__ float LPart[2 * 64 * 4 * 64];

// ============================ helpers =================================
__device__ __forceinline__ void split2(float x, f16& h, f16& l) {
    h = __float2half(x);
    l = __float2half(x - __half2float(h));
}
__device__ __forceinline__ uint32 pk(f16 a, f16 b) {
    __half2 v(a, b);
    return *(uint32*)&v;
}
__device__ __forceinline__ void mma_f16(float c[4], const uint32 a[4],
                                        const uint32 b[2]) {
    asm volatile(
        "mma.sync.aligned.m16n8k16.row.col.f32.f16.f16.f32 "
        "{%0,%1,%2,%3}, {%4,%5,%6,%7}, {%8,%9}, {%0,%1,%2,%3};"
        : "+f"(c[0]), "+f"(c[1]), "+f"(c[2]), "+f"(c[3])
        : "r"(a[0]), "r"(a[1]), "r"(a[2]), "r"(a[3]), "r"(b[0]), "r"(b[1]));
}

// ======================================================================
// GEMM core for projections: 3-pass fp16 split (error ~2^-22).
// ======================================================================
#define RS   72
#define PL   18432
#define SMEM_GEMM (4 * PL)

__device__ __forceinline__ void gemm128(
    const f16* __restrict__ Agh, const f16* __restrict__ Agl, size_t sA,
    const f16* __restrict__ Bgh, const f16* __restrict__ Bgl, size_t sB,
    int nchunk, char* smem, float acc[16][4])
{
    f16* sAh = (f16*)(smem);
    f16* sAl = (f16*)(smem + PL);
    f16* sBh = (f16*)(smem + 2 * PL);
    f16* sBl = (f16*)(smem + 3 * PL);
    const int t = threadIdx.x;
    const int wid = t >> 5, lane = t & 31;
    const int wm = wid >> 2, wn = wid & 3;
    const int gr = lane >> 2, tc = lane & 3;

    int row[4], c8[4];
#pragma unroll
    for (int i = 0; i < 4; i++) { int u = t + 256 * i; row[i] = u >> 3; c8[i] = u & 7; }

    float4 p0[4], p1[4], p2[4], p3[4];
#define GLOAD(k0) {                                                            \
    _Pragma("unroll") for (int i_ = 0; i_ < 4; i_++) {                         \
        p0[i_] = *(const float4*)(Agh + (size_t)row[i_] * sA + (k0) + c8[i_] * 8); \
        p1[i_] = *(const float4*)(Agl + (size_t)row[i_] * sA + (k0) + c8[i_] * 8); \
        p2[i_] = *(const float4*)(Bgh + (size_t)row[i_] * sB + (k0) + c8[i_] * 8); \
        p3[i_] = *(const float4*)(Bgl + (size_t)row[i_] * sB + (k0) + c8[i_] * 8); \
    } }

    GLOAD(0);
    for (int ch = 0; ch < nchunk; ch++) {
        __syncthreads();
#pragma unroll
        for (int i = 0; i < 4; i++) {
            int off = row[i] * RS + c8[i] * 8;
            *(float4*)(sAh + off) = p0[i];
            *(float4*)(sAl + off) = p1[i];
            *(float4*)(sBh + off) = p2[i];
            *(float4*)(sBl + off) = p3[i];
        }
        __syncthreads();
        if (ch + 1 < nchunk) GLOAD((ch + 1) * 64);

#pragma unroll
        for (int ks = 0; ks < 4; ks++) {
            uint32 ah[4][4], al[4][4], bh[4][2], bl[4][2];
#pragma unroll
            for (int mf = 0; mf < 4; mf++) {
                int o = (wm * 64 + mf * 16 + gr) * RS + ks * 16 + 2 * tc;
                ah[mf][0] = *(const uint32*)(sAh + o);
                ah[mf][1] = *(const uint32*)(sAh + o + 8 * RS);
                ah[mf][2] = *(const uint32*)(sAh + o + 8);
                ah[mf][3] = *(const uint32*)(sAh + o + 8 * RS + 8);
                al[mf][0] = *(const uint32*)(sAl + o);
                al[mf][1] = *(const uint32*)(sAl + o + 8 * RS);
                al[mf][2] = *(const uint32*)(sAl + o + 8);
                al[mf][3] = *(const uint32*)(sAl + o + 8 * RS + 8);
            }
#pragma unroll
            for (int nf = 0; nf < 4; nf++) {
                int o = (wn * 32 + nf * 8 + gr) * RS + ks * 16 + 2 * tc;
                bh[nf][0] = *(const uint32*)(sBh + o);
                bh[nf][1] = *(const uint32*)(sBh + o + 8);
                bl[nf][0] = *(const uint32*)(sBl + o);
                bl[nf][1] = *(const uint32*)(sBl + o + 8);
            }
#pragma unroll
            for (int mf = 0; mf < 4; mf++)
#pragma unroll
                for (int nf = 0; nf < 4; nf++) {
                    mma_f16(acc[mf * 4 + nf], ah[mf], bh[nf]);
                    mma_f16(acc[mf * 4 + nf], ah[mf], bl[nf]);
                    mma_f16(acc[mf * 4 + nf], al[mf], bh[nf]);
                }
        }
    }
#undef GLOAD
}

// ============================ kernel 1: convert X =====================
__global__ __launch_bounds__(256) void cvt_x(const float* __restrict__ X) {
    const int N4 = 8192 * 1024 / 4;
    for (int i = blockIdx.x * 256 + threadIdx.x; i < N4; i += 2048 * 256) {
        float4 x = ((const float4*)X)[i];
        f16 h0, l0, h1, l1, h2, l2, h3, l3;
        split2(x.x, h0, l0); split2(x.y, h1, l1);
        split2(x.z, h2, l2); split2(x.w, h3, l3);
        ((uint2*)Xh)[i] = make_uint2(pk(h0, h1), pk(h2, h3));
        ((uint2*)Xl)[i] = make_uint2(pk(l0, l1), pk(l2, l3));
    }
}

// ============================ kernel 2: convert+transpose W ===========
__global__ void cvt_w(const float* __restrict__ Wq, const float* __restrict__ Wk,
                      const float* __restrict__ Wv) {
    __shared__ float tile[32][33];
    const int pj = blockIdx.z;
    const float* W = (pj == 0) ? Wq : (pj == 1) ? Wk : Wv;
    const int k0 = blockIdx.x * 32, n0 = blockIdx.y * 32;
    const int tx = threadIdx.x, ty = threadIdx.y;
#pragma unroll
    for (int i = 0; i < 4; i++)
        tile[ty + 8 * i][tx] = W[(k0 + ty + 8 * i) * 256 + n0 + tx];
    __syncthreads();
#pragma unroll
    for (int i = 0; i < 4; i++) {
        int n = n0 + ty + 8 * i;
        f16 h, l;
        split2(tile[tx][ty + 8 * i], h, l);
        Wth[pj * 262144 + n * 1024 + k0 + tx] = h;
        Wtl[pj * 262144 + n * 1024 + k0 + tx] = l;
    }
}

// ============================ kernel 3: projection GEMM ===============
__global__ __launch_bounds__(256) void proj_mma() {
    extern __shared__ char smem[];
    const int m0 = (blockIdx.x >> 1) * 128;
    const int nb = blockIdx.x & 1;
    const int pj = blockIdx.y;

    float acc[16][4];
#pragma unroll
    for (int i = 0; i < 16; i++)
#pragma unroll
        for (int j = 0; j < 4; j++) acc[i][j] = 0.f;

    gemm128(Xh + (size_t)m0 * 1024, Xl + (size_t)m0 * 1024, 1024,
            Wth + pj * 262144 + (size_t)(nb * 128) * 1024,
            Wtl + pj * 262144 + (size_t)(nb * 128) * 1024, 1024,
            16, smem, acc);

    f16* dh = (pj == 0) ? Qh : (pj == 1) ? Kh : Vh;

    const int t = threadIdx.x, wid = t >> 5, lane = t & 31;
    const int wm = wid >> 2, wn = wid & 3;
    const int gr = lane >> 2, tc = lane & 3;
#pragma unroll
    for (int mf = 0; mf < 4; mf++)
#pragma unroll
        for (int nf = 0; nf < 4; nf++)
#pragma unroll
            for (int h = 0; h < 2; h++) {
                int m = m0 + wm * 64 + mf * 16 + gr + 8 * h;
                int n = nb * 128 + wn * 32 + nf * 8 + 2 * tc;
                int s = m >> 1, b = m & 1;
                float v0 = acc[mf * 4 + nf][2 * h];
                float v1 = acc[mf * 4 + nf][2 * h + 1];
                size_t o = ((size_t)b * 4096 + s) * 256 + n;
                *(uint32*)(dh + o) = pk(__float2half(v0), __float2half(v1));
            }
}

// ============================ kernel 4: V transpose (hi only) =========
__global__ __launch_bounds__(256) void vtrans() {
    __shared__ f16 tile[64][80];
    const int t = threadIdx.x;
    const int s0 = blockIdx.x * 64, d0 = blockIdx.y * 64;
    const int b = blockIdx.z;
#pragma unroll
    for (int i = 0; i < 2; i++) {
        int u = t + 256 * i, row = u >> 3, c8 = u & 7;
        float4 x = *(const float4*)(Vh + ((size_t)b * 4096 + s0 + row) * 256 + d0 + c8 * 8);
        *(float4*)&tile[row][c8 * 8] = x;
    }
    __syncthreads();
#pragma unroll
    for (int i = 0; i < 2; i++) {
        int u = t + 256 * i, d = u >> 3, g8 = u & 7;
        f16 tmp[8];
#pragma unroll
        for (int j = 0; j < 8; j++) tmp[j] = tile[g8 * 8 + j][d];
        *(float4*)(Vth + ((size_t)b * 256 + d0 + d) * 4096 + s0 + g8 * 8) = *(float4*)tmp;
    }
}

// ======================================================================
// Kernel 5: fused flash attention, pure fp16 1-pass both stages.
//   S = Qh·Kh  (score abs err ~3.4e-4), O = Ph·Vh.
// CTA: 64-query tile, split-K chunk of 8 key-tiles (1024 keys).
// 8 warps 2x4: S warp-tile 32x32, O warp-tile 32x64.
// ======================================================================
#define F_QH 0
#define F_KH 9216           // S phase region ends 27648
#define F_VH 0              // V overlays Q/K region (36864 bytes)
#define F_PH 36864          // 64 x 68 uint32 = 17408 bytes
#define F_MX 54272          // 64 x 4 floats
#define F_SZ 55296

__global__ __launch_bounds__(256) void fa_mma() {
    extern __shared__ char sm[];
    const int t = threadIdx.x, wid = t >> 5, lane = t & 31;
    const int wm = wid >> 2, wn = wid & 3;
    const int gr = lane >> 2, tc = lane & 3;
    const int b = blockIdx.y;

    // chunk decode (reversed: biggest qi first); CHUNK = 8 key-tiles
    const int n = 159 - blockIdx.x;
    int qi, c;
    if (n < 16)      { qi = n;                  c = 0; }
    else if (n < 48) { int m_ = n - 16; qi = 16 + (m_ >> 1); c = m_ & 1; }
    else if (n < 96) { int m_ = n - 48; qi = 32 + m_ / 3;    c = m_ % 3; }
    else             { int m_ = n - 96; qi = 48 + (m_ >> 2); c = m_ & 3; }

    const int kt_diag = qi >> 1;
    const int kt0 = c * 8;
    const int kt1 = min(kt0 + 8, kt_diag + 1);
    const int q0 = qi * 64;

    float acc_o[2][8][4];
#pragma unroll
    for (int mf = 0; mf < 2; mf++)
#pragma unroll
        for (int nf = 0; nf < 8; nf++)
#pragma unroll
            for (int ci = 0; ci < 4; ci++) acc_o[mf][nf][ci] = 0.f;
    float m[4] = {-INFINITY, -INFINITY, -INFINITY, -INFINITY};
    float l[4] = {0.f, 0.f, 0.f, 0.f};

    const uint32* qh32 = (const uint32*)(sm + F_QH);
    const uint32* kh32 = (const uint32*)(sm + F_KH);
    const uint32* vh32 = (const uint32*)(sm + F_VH);
    uint32* ph32 = (uint32*)(sm + F_PH);
    float* pmax = (float*)(sm + F_MX);

    for (int kt = kt0; kt < kt1; kt++) {
        const bool diag = (kt == kt_diag);

        // ---------------- S = Q K^T over 4 d-chunks ----------------
        float acc_s[2][4][4];
#pragma unroll
        for (int mf = 0; mf < 2; mf++)
#pragma unroll
            for (int nf = 0; nf < 4; nf++)
#pragma unroll
                for (int ci = 0; ci < 4; ci++) acc_s[mf][nf][ci] = 0.f;

        for (int dc = 0; dc < 4; dc++) {
            const int d0 = dc * 64;
            float4 rq[2], rk[4];
#pragma unroll
            for (int i = 0; i < 2; i++) {
                int u = t + 256 * i, r = u >> 3, c8 = u & 7;
                rq[i] = *(const float4*)(Qh + ((size_t)(b * 4096 + q0 + r)) * 256 + d0 + c8 * 8);
            }
#pragma unroll
            for (int i = 0; i < 4; i++) {
                int u = t + 256 * i, r = u >> 3, c8 = u & 7;
                rk[i] = *(const float4*)(Kh + ((size_t)(b * 4096 + kt * 128 + r)) * 256 + d0 + c8 * 8);
            }
            __syncthreads();   // previous readers of this smem done
#pragma unroll
            for (int i = 0; i < 2; i++) {
                int u = t + 256 * i, r = u >> 3, c8 = u & 7;
                *(float4*)(sm + F_QH + r * 144 + c8 * 16) = rq[i];
            }
#pragma unroll
            for (int i = 0; i < 4; i++) {
                int u = t + 256 * i, r = u >> 3, c8 = u & 7;
                *(float4*)(sm + F_KH + r * 144 + c8 * 16) = rk[i];
            }
            __syncthreads();

#pragma unroll
            for (int ks = 0; ks < 4; ks++) {
                uint32 ah[2][4], bh[4][2];
#pragma unroll
                for (int mf = 0; mf < 2; mf++) {
                    int o = (wm * 32 + mf * 16 + gr) * 36 + ks * 8 + tc;
                    ah[mf][0] = qh32[o];          ah[mf][1] = qh32[o + 8 * 36];
                    ah[mf][2] = qh32[o + 4];      ah[mf][3] = qh32[o + 8 * 36 + 4];
                }
#pragma unroll
                for (int nf = 0; nf < 4; nf++) {
                    int o = (wn * 32 + nf * 8 + gr) * 36 + ks * 8 + tc;
                    bh[nf][0] = kh32[o];  bh[nf][1] = kh32[o + 4];
                }
#pragma unroll
                for (int mf = 0; mf < 2; mf++)
#pragma unroll
                    for (int nf = 0; nf < 4; nf++)
                        mma_f16(acc_s[mf][nf], ah[mf], bh[nf]);
            }
        }

        // ---------------- scale + mask + row-max ----------------
        float pm[4] = {-1e30f, -1e30f, -1e30f, -1e30f};
#pragma unroll
        for (int mf = 0; mf < 2; mf++)
#pragma unroll
            for (int nf = 0; nf < 4; nf++)
#pragma unroll
                for (int ci = 0; ci < 4; ci++) {
                    float s = acc_s[mf][nf][ci] * 0.0625f;
                    if (diag) {
                        int qg = q0 + wm * 32 + mf * 16 + gr + (ci >> 1) * 8;
                        int kg = kt * 128 + wn * 32 + nf * 8 + 2 * tc + (ci & 1);
                        if (kg > qg) s = -1e30f;
                    }
                    acc_s[mf][nf][ci] = s;
                    int ri = mf * 2 + (ci >> 1);
                    pm[ri] = fmaxf(pm[ri], s);
                }
#pragma unroll
        for (int i = 0; i < 4; i++) {
            pm[i] = fmaxf(pm[i], __shfl_xor_sync(~0u, pm[i], 1));
            pm[i] = fmaxf(pm[i], __shfl_xor_sync(~0u, pm[i], 2));
        }
        if (tc == 0) {
#pragma unroll
            for (int i = 0; i < 4; i++) {
                int row = wm * 32 + (i >> 1) * 16 + (i & 1) * 8 + gr;
                pmax[row * 4 + wn] = pm[i];
            }
        }
        __syncthreads();   // pmax visible; S-phase smem reads done

        float alpha[4];
#pragma unroll
        for (int i = 0; i < 4; i++) {
            int row = wm * 32 + (i >> 1) * 16 + (i & 1) * 8 + gr;
            float mt = fmaxf(fmaxf(pmax[row * 4 + 0], pmax[row * 4 + 1]),
                             fmaxf(pmax[row * 4 + 2], pmax[row * 4 + 3]));
            float m_new = fmaxf(m[i], mt);
            alpha[i] = __expf(m[i] - m_new);
            m[i] = m_new;
            l[i] *= alpha[i];
        }
#pragma unroll
        for (int mf = 0; mf < 2; mf++)
#pragma unroll
            for (int nf = 0; nf < 8; nf++)
#pragma unroll
                for (int ci = 0; ci < 4; ci++)
                    acc_o[mf][nf][ci] *= alpha[mf * 2 + (ci >> 1)];

        // ---------------- exp -> P (fp16) into smem ----------------
#pragma unroll
        for (int mf = 0; mf < 2; mf++)
#pragma unroll
            for (int nf = 0; nf < 4; nf++)
#pragma unroll
                for (int h = 0; h < 2; h++) {
                    int ri = mf * 2 + h;
                    float p0 = __expf(acc_s[mf][nf][h * 2 + 0] - m[ri]);
                    float p1 = __expf(acc_s[mf][nf][h * 2 + 1] - m[ri]);
                    l[ri] += p0 + p1;
                    int row = wm * 32 + mf * 16 + h * 8 + gr;
                    ph32[row * 68 + wn * 16 + nf * 4 + tc] =
                        pk(__float2half(p0), __float2half(p1));
                }

        // ---------------- PV over 2 key-chunks ----------------
#pragma unroll
        for (int kc = 0; kc < 2; kc++) {
            float4 rv[8];
#pragma unroll
            for (int i = 0; i < 8; i++) {
                int u = t + 256 * i, d = u >> 3, c8 = u & 7;
                rv[i] = *(const float4*)(Vth + ((size_t)(b * 256 + d)) * 4096
                                         + kt * 128 + kc * 64 + c8 * 8);
            }
            __syncthreads();   // prior readers of V region done
#pragma unroll
            for (int i = 0; i < 8; i++) {
                int u = t + 256 * i, d = u >> 3, c8 = u & 7;
                *(float4*)(sm + F_VH + d * 144 + c8 * 16) = rv[i];
            }
            __syncthreads();   // V + P visible

#pragma unroll
            for (int ks = 0; ks < 4; ks++) {
                uint32 ah[2][4], bh[8][2];
#pragma unroll
                for (int mf = 0; mf < 2; mf++) {
                    int o = (wm * 32 + mf * 16 + gr) * 68 + kc * 32 + ks * 8 + tc;
                    ah[mf][0] = ph32[o];      ah[mf][1] = ph32[o + 8 * 68];
                    ah[mf][2] = ph32[o + 4];  ah[mf][3] = ph32[o + 8 * 68 + 4];
                }
#pragma unroll
                for (int nf = 0; nf < 8; nf++) {
                    int o = (wn * 64 + nf * 8 + gr) * 36 + ks * 8 + tc;
                    bh[nf][0] = vh32[o];  bh[nf][1] = vh32[o + 4];
                }
#pragma unroll
                for (int mf = 0; mf < 2; mf++)
#pragma unroll
                    for (int nf = 0; nf < 8; nf++)
                        mma_f16(acc_o[mf][nf], ah[mf], bh[nf]);
            }
        }
        __syncthreads();   // PV reads done before next ktile's smem stores
    }

    // ---------------- epilogue: reduce l, write partials ----------------
#pragma unroll
    for (int i = 0; i < 4; i++) {
        l[i] += __shfl_xor_sync(~0u, l[i], 1);
        l[i] += __shfl_xor_sync(~0u, l[i], 2);
    }
    if (tc == 0) {
#pragma unroll
        for (int i = 0; i < 4; i++) {
            int row = wm * 32 + (i >> 1) * 16 + (i & 1) * 8 + gr;
            pmax[row * 4 + wn] = l[i];
        }
    }
    __syncthreads();

    const size_t pb = ((size_t)(b * 64 + qi) * 4 + c) * 64;
#pragma unroll
    for (int i = 0; i < 4; i++) {
        int row = wm * 32 + (i >> 1) * 16 + (i & 1) * 8 + gr;
        if (wn == 0 && tc == 0) {
            float lr = pmax[row * 4 + 0] + pmax[row * 4 + 1] +
                       pmax[row * 4 + 2] + pmax[row * 4 + 3];
            MPart[pb + row] = m[i];
            LPart[pb + row] = lr;
        }
    }
#pragma unroll
    for (int mf = 0; mf < 2; mf++)
#pragma unroll
        for (int h = 0; h < 2; h++) {
            int row = wm * 32 + mf * 16 + h * 8 + gr;
            float* orow = OPart + (pb + row) * 256;
#pragma unroll
            for (int nf = 0; nf < 8; nf++) {
                float2 v = make_float2(acc_o[mf][nf][h * 2 + 0],
                                       acc_o[mf][nf][h * 2 + 1]);
                *(float2*)(orow + wn * 64 + nf * 8 + 2 * tc) = v;
            }
        }
}

// ============================ kernel 6: combine =======================
__global__ __launch_bounds__(256) void combine_k(float* __restrict__ out) {
    const int t = threadIdx.x;
    const int R = blockIdx.x * 4 + (t >> 6);   // = q*2 + b
    const int q = R >> 1, b = R & 1;
    const int qi = q >> 6, r = q & 63;
    const int nc = (qi >> 4) + 1;
    const size_t cb = ((size_t)(b * 64 + qi) * 4) * 64 + r;

    float mx = -INFINITY;
    for (int c = 0; c < nc; c++) mx = fmaxf(mx, MPart[cb + (size_t)c * 64]);
    float w[4];
    float denom = 0.f;
    for (int c = 0; c < nc; c++) {
        w[c] = __expf(MPart[cb + (size_t)c * 64] - mx);
        denom += w[c] * LPart[cb + (size_t)c * 64];
    }
    const float inv = 1.f / denom;

    const int d = (t & 63) * 4;
    float4 acc = make_float4(0.f, 0.f, 0.f, 0.f);
    for (int c = 0; c < nc; c++) {
        const float4 v = *(const float4*)
            (OPart + (cb + (size_t)c * 64) * 256 + d);
        acc.x += w[c] * v.x; acc.y += w[c] * v.y;
        acc.z += w[c] * v.z; acc.w += w[c] * v.w;
    }
    acc.x *= inv; acc.y *= inv; acc.z *= inv; acc.w *= inv;
    *(float4*)(out + (size_t)R * 256 + d) = acc;
}

// ============================ launch ==================================
extern "C" void kernel_launch(void* const* d_in, const int* in_sizes, int n_in,
                              void* d_out, int out_size) {
    const float* x  = (const float*)d_in[0];
    const float* Wq = (const float*)d_in[2];
    const float* Wk = (const float*)d_in[3];
    const float* Wv = (const float*)d_in[4];
    float* out = (float*)d_out;

    cudaFuncSetAttribute(proj_mma, cudaFuncAttributeMaxDynamicSharedMemorySize, SMEM_GEMM);
    cudaFuncSetAttribute(fa_mma,   cudaFuncAttributeMaxDynamicSharedMemorySize, F_SZ);

    cvt_x<<<2048, 256>>>(x);
    cvt_w<<<dim3(32, 8, 3), dim3(32, 8)>>>(Wq, Wk, Wv);
    proj_mma<<<dim3(128, 3), 256, SMEM_GEMM>>>();
    vtrans<<<dim3(64, 4, 2), 256>>>();
    fa_mma<<<dim3(160, 2), 256, F_SZ>>>();
    combine_k<<<2048, 256>>>(out);
}

// round 9
// speedup vs baseline: 5.5216x; 1.2697x over previous
#include <cuda_runtime.h>
#include <cuda_fp16.h>
#include <math.h>
#include <stdint.h>

typedef __half f16;
typedef unsigned int uint32;

// ============================ scratch =================================
__device__ f16   Xh[8192 * 1024];
__device__ f16   Wth[3 * 256 * 1024], Wtl[3 * 256 * 1024];   // W^T [proj][n][k]
__device__ f16   Qh[2 * 4096 * 256];
__device__ f16   Kh[2 * 4096 * 256];
__device__ f16   Vh[2 * 4096 * 256];
__device__ f16   Vth[2 * 256 * 4096];                        // V^T [b][d][s]
__device__ float OPart[2ull * 64 * 4 * 64 * 256];            // split-K partials
__device__ float MPart[2 * 64 * 4 * 64];
__device__ float LPart[2 * 64 * 4 * 64];

// ============================ helpers =================================
__device__ __forceinline__ void split2(float x, f16& h, f16& l) {
    h = __float2half(x);
    l = __float2half(x - __half2float(h));
}
__device__ __forceinline__ uint32 pk(f16 a, f16 b) {
    __half2 v(a, b);
    return *(uint32*)&v;
}
__device__ __forceinline__ void mma_f16(float c[4], const uint32 a[4],
                                        const uint32 b[2]) {
    asm volatile(
        "mma.sync.aligned.m16n8k16.row.col.f32.f16.f16.f32 "
        "{%0,%1,%2,%3}, {%4,%5,%6,%7}, {%8,%9}, {%0,%1,%2,%3};"
        : "+f"(c[0]), "+f"(c[1]), "+f"(c[2]), "+f"(c[3])
        : "r"(a[0]), "r"(a[1]), "r"(a[2]), "r"(a[3]), "r"(b[0]), "r"(b[1]));
}

// ======================================================================
// GEMM core for projections: 2-pass fp16 split  C ≈ Ah·(Bh + Bl).
// (dropped Al·B term ≈ 2.8e-4 relative on Q/K/V — within error budget)
// ======================================================================
#define RS   72
#define PL   18432
#define SMEM_GEMM (3 * PL)

__device__ __forceinline__ void gemm128(
    const f16* __restrict__ Agh, size_t sA,
    const f16* __restrict__ Bgh, const f16* __restrict__ Bgl, size_t sB,
    int nchunk, char* smem, float acc[16][4])
{
    f16* sAh = (f16*)(smem);
    f16* sBh = (f16*)(smem + PL);
    f16* sBl = (f16*)(smem + 2 * PL);
    const int t = threadIdx.x;
    const int wid = t >> 5, lane = t & 31;
    const int wm = wid >> 2, wn = wid & 3;
    const int gr = lane >> 2, tc = lane & 3;

    int row[4], c8[4];
#pragma unroll
    for (int i = 0; i < 4; i++) { int u = t + 256 * i; row[i] = u >> 3; c8[i] = u & 7; }

    float4 p0[4], p2[4], p3[4];
#define GLOAD(k0) {                                                            \
    _Pragma("unroll") for (int i_ = 0; i_ < 4; i_++) {                         \
        p0[i_] = *(const float4*)(Agh + (size_t)row[i_] * sA + (k0) + c8[i_] * 8); \
        p2[i_] = *(const float4*)(Bgh + (size_t)row[i_] * sB + (k0) + c8[i_] * 8); \
        p3[i_] = *(const float4*)(Bgl + (size_t)row[i_] * sB + (k0) + c8[i_] * 8); \
    } }

    GLOAD(0);
    for (int ch = 0; ch < nchunk; ch++) {
        __syncthreads();
#pragma unroll
        for (int i = 0; i < 4; i++) {
            int off = row[i] * RS + c8[i] * 8;
            *(float4*)(sAh + off) = p0[i];
            *(float4*)(sBh + off) = p2[i];
            *(float4*)(sBl + off) = p3[i];
        }
        __syncthreads();
        if (ch + 1 < nchunk) GLOAD((ch + 1) * 64);

#pragma unroll
        for (int ks = 0; ks < 4; ks++) {
            uint32 ah[4][4], bh[4][2], bl[4][2];
#pragma unroll
            for (int mf = 0; mf < 4; mf++) {
                int o = (wm * 64 + mf * 16 + gr) * RS + ks * 16 + 2 * tc;
                ah[mf][0] = *(const uint32*)(sAh + o);
                ah[mf][1] = *(const uint32*)(sAh + o + 8 * RS);
                ah[mf][2] = *(const uint32*)(sAh + o + 8);
                ah[mf][3] = *(const uint32*)(sAh + o + 8 * RS + 8);
            }
#pragma unroll
            for (int nf = 0; nf < 4; nf++) {
                int o = (wn * 32 + nf * 8 + gr) * RS + ks * 16 + 2 * tc;
                bh[nf][0] = *(const uint32*)(sBh + o);
                bh[nf][1] = *(const uint32*)(sBh + o + 8);
                bl[nf][0] = *(const uint32*)(sBl + o);
                bl[nf][1] = *(const uint32*)(sBl + o + 8);
            }
#pragma unroll
            for (int mf = 0; mf < 4; mf++)
#pragma unroll
                for (int nf = 0; nf < 4; nf++) {
                    mma_f16(acc[mf * 4 + nf], ah[mf], bh[nf]);
                    mma_f16(acc[mf * 4 + nf], ah[mf], bl[nf]);
                }
        }
    }
#undef GLOAD
}

// ============================ kernel 1: convert X (hi only) ===========
__global__ __launch_bounds__(256) void cvt_x(const float* __restrict__ X) {
    const int N4 = 8192 * 1024 / 4;
    for (int i = blockIdx.x * 256 + threadIdx.x; i < N4; i += 2048 * 256) {
        float4 x = ((const float4*)X)[i];
        ((uint2*)Xh)[i] = make_uint2(
            pk(__float2half(x.x), __float2half(x.y)),
            pk(__float2half(x.z), __float2half(x.w)));
    }
}

// ============================ kernel 2: convert+transpose W ===========
__global__ void cvt_w(const float* __restrict__ Wq, const float* __restrict__ Wk,
                      const float* __restrict__ Wv) {
    __shared__ float tile[32][33];
    const int pj = blockIdx.z;
    const float* W = (pj == 0) ? Wq : (pj == 1) ? Wk : Wv;
    const int k0 = blockIdx.x * 32, n0 = blockIdx.y * 32;
    const int tx = threadIdx.x, ty = threadIdx.y;
#pragma unroll
    for (int i = 0; i < 4; i++)
        tile[ty + 8 * i][tx] = W[(k0 + ty + 8 * i) * 256 + n0 + tx];
    __syncthreads();
#pragma unroll
    for (int i = 0; i < 4; i++) {
        int n = n0 + ty + 8 * i;
        f16 h, l;
        split2(tile[tx][ty + 8 * i], h, l);
        Wth[pj * 262144 + n * 1024 + k0 + tx] = h;
        Wtl[pj * 262144 + n * 1024 + k0 + tx] = l;
    }
}

// ============================ kernel 3: projection GEMM ===============
__global__ __launch_bounds__(256) void proj_mma() {
    extern __shared__ char smem[];
    const int m0 = (blockIdx.x >> 1) * 128;
    const int nb = blockIdx.x & 1;
    const int pj = blockIdx.y;

    float acc[16][4];
#pragma unroll
    for (int i = 0; i < 16; i++)
#pragma unroll
        for (int j = 0; j < 4; j++) acc[i][j] = 0.f;

    gemm128(Xh + (size_t)m0 * 1024, 1024,
            Wth + pj * 262144 + (size_t)(nb * 128) * 1024,
            Wtl + pj * 262144 + (size_t)(nb * 128) * 1024, 1024,
            16, smem, acc);

    f16* dh = (pj == 0) ? Qh : (pj == 1) ? Kh : Vh;

    const int t = threadIdx.x, wid = t >> 5, lane = t & 31;
    const int wm = wid >> 2, wn = wid & 3;
    const int gr = lane >> 2, tc = lane & 3;
#pragma unroll
    for (int mf = 0; mf < 4; mf++)
#pragma unroll
        for (int nf = 0; nf < 4; nf++)
#pragma unroll
            for (int h = 0; h < 2; h++) {
                int m = m0 + wm * 64 + mf * 16 + gr + 8 * h;
                int n = nb * 128 + wn * 32 + nf * 8 + 2 * tc;
                int s = m >> 1, b = m & 1;
                float v0 = acc[mf * 4 + nf][2 * h];
                float v1 = acc[mf * 4 + nf][2 * h + 1];
                size_t o = ((size_t)b * 4096 + s) * 256 + n;
                *(uint32*)(dh + o) = pk(__float2half(v0), __float2half(v1));
            }
}

// ============================ kernel 4: V transpose ===================
__global__ __launch_bounds__(256) void vtrans() {
    __shared__ f16 tile[64][80];
    const int t = threadIdx.x;
    const int s0 = blockIdx.x * 64, d0 = blockIdx.y * 64;
    const int b = blockIdx.z;
#pragma unroll
    for (int i = 0; i < 2; i++) {
        int u = t + 256 * i, row = u >> 3, c8 = u & 7;
        float4 x = *(const float4*)(Vh + ((size_t)b * 4096 + s0 + row) * 256 + d0 + c8 * 8);
        *(float4*)&tile[row][c8 * 8] = x;
    }
    __syncthreads();
#pragma unroll
    for (int i = 0; i < 2; i++) {
        int u = t + 256 * i, d = u >> 3, g8 = u & 7;
        f16 tmp[8];
#pragma unroll
        for (int j = 0; j < 8; j++) tmp[j] = tile[g8 * 8 + j][d];
        *(float4*)(Vth + ((size_t)b * 256 + d0 + d) * 4096 + s0 + g8 * 8) = *(float4*)tmp;
    }
}

// ======================================================================
// Kernel 5: fused flash attention — resident-tile version.
// Q (64x256) persistent in smem; K (128x256) and V^T (256x128) loaded
// whole per k-tile. 4 syncs per k-tile (was 14). fp16 1-pass mma.
// ======================================================================
#define SQ_  0              // Q: 64 rows, 528 B stride = 33792
#define SK_  33792          // K: 128 rows, 528 B stride = 67584
#define SV_  101376         // V: 256 rows, 272 B stride = 69632
#define SP_  171008         // P: 64 x 68 uint32 = 17408
#define SMX_ 188416         // 64 x 4 floats
#define FSZ  189440

__global__ __launch_bounds__(256) void fa_mma() {
    extern __shared__ char sm[];
    const int t = threadIdx.x, wid = t >> 5, lane = t & 31;
    const int wm = wid >> 2, wn = wid & 3;
    const int gr = lane >> 2, tc = lane & 3;
    const int b = blockIdx.y;

    // chunk decode (reversed: biggest qi first); CHUNK = 8 key-tiles
    const int n = 159 - blockIdx.x;
    int qi, c;
    if (n < 16)      { qi = n;                  c = 0; }
    else if (n < 48) { int m_ = n - 16; qi = 16 + (m_ >> 1); c = m_ & 1; }
    else if (n < 96) { int m_ = n - 48; qi = 32 + m_ / 3;    c = m_ % 3; }
    else             { int m_ = n - 96; qi = 48 + (m_ >> 2); c = m_ & 3; }

    const int kt_diag = qi >> 1;
    const int kt0 = c * 8;
    const int kt1 = min(kt0 + 8, kt_diag + 1);
    const int q0 = qi * 64;

    const uint32* q32 = (const uint32*)(sm + SQ_);
    const uint32* k32 = (const uint32*)(sm + SK_);
    const uint32* v32 = (const uint32*)(sm + SV_);
    uint32* p32 = (uint32*)(sm + SP_);
    float* pmax = (float*)(sm + SMX_);

    // ---- load Q once (64 x 256 f16) ----
#pragma unroll
    for (int i = 0; i < 8; i++) {
        int u = t + 256 * i, row = u >> 5, c16 = u & 31;
        *(float4*)(sm + SQ_ + row * 528 + c16 * 16) =
            *(const float4*)(Qh + ((size_t)(b * 4096 + q0 + row)) * 256 + c16 * 8);
    }

    float acc_o[2][8][4];
#pragma unroll
    for (int mf = 0; mf < 2; mf++)
#pragma unroll
        for (int nf = 0; nf < 8; nf++)
#pragma unroll
            for (int ci = 0; ci < 4; ci++) acc_o[mf][nf][ci] = 0.f;
    float m[4] = {-INFINITY, -INFINITY, -INFINITY, -INFINITY};
    float l[4] = {0.f, 0.f, 0.f, 0.f};

    for (int kt = kt0; kt < kt1; kt++) {
        const bool diag = (kt == kt_diag);

        __syncthreads();   // prior iter's S/PV smem reads done (covers Q stores on iter 0)
        // ---- K tile: 128 x 256 f16 ----
#pragma unroll
        for (int i = 0; i < 16; i++) {
            int u = t + 256 * i, row = u >> 5, c16 = u & 31;
            *(float4*)(sm + SK_ + row * 528 + c16 * 16) =
                *(const float4*)(Kh + ((size_t)(b * 4096 + kt * 128 + row)) * 256 + c16 * 8);
        }
        // ---- V tile: V^T 256 x 128 f16 ----
#pragma unroll
        for (int i = 0; i < 16; i++) {
            int u = t + 256 * i, d = u >> 4, c16 = u & 15;
            *(float4*)(sm + SV_ + d * 272 + c16 * 16) =
                *(const float4*)(Vth + ((size_t)(b * 256 + d)) * 4096 + kt * 128 + c16 * 8);
        }
        __syncthreads();

        // ---------------- S = Q K^T (all from smem, no syncs) ----------------
        float acc_s[2][4][4];
#pragma unroll
        for (int mf = 0; mf < 2; mf++)
#pragma unroll
            for (int nf = 0; nf < 4; nf++)
#pragma unroll
                for (int ci = 0; ci < 4; ci++) acc_s[mf][nf][ci] = 0.f;

#pragma unroll
        for (int dc = 0; dc < 4; dc++)
#pragma unroll
            for (int ks = 0; ks < 4; ks++) {
                uint32 ah[2][4], bh[4][2];
#pragma unroll
                for (int mf = 0; mf < 2; mf++) {
                    int o = (wm * 32 + mf * 16 + gr) * 132 + dc * 32 + ks * 8 + tc;
                    ah[mf][0] = q32[o];          ah[mf][1] = q32[o + 8 * 132];
                    ah[mf][2] = q32[o + 4];      ah[mf][3] = q32[o + 8 * 132 + 4];
                }
#pragma unroll
                for (int nf = 0; nf < 4; nf++) {
                    int o = (wn * 32 + nf * 8 + gr) * 132 + dc * 32 + ks * 8 + tc;
                    bh[nf][0] = k32[o];  bh[nf][1] = k32[o + 4];
                }
#pragma unroll
                for (int mf = 0; mf < 2; mf++)
#pragma unroll
                    for (int nf = 0; nf < 4; nf++)
                        mma_f16(acc_s[mf][nf], ah[mf], bh[nf]);
            }

        // ---------------- scale + mask + row-max ----------------
        float pm[4] = {-1e30f, -1e30f, -1e30f, -1e30f};
#pragma unroll
        for (int mf = 0; mf < 2; mf++)
#pragma unroll
            for (int nf = 0; nf < 4; nf++)
#pragma unroll
                for (int ci = 0; ci < 4; ci++) {
                    float s = acc_s[mf][nf][ci] * 0.0625f;
                    if (diag) {
                        int qg = q0 + wm * 32 + mf * 16 + gr + (ci >> 1) * 8;
                        int kg = kt * 128 + wn * 32 + nf * 8 + 2 * tc + (ci & 1);
                        if (kg > qg) s = -1e30f;
                    }
                    acc_s[mf][nf][ci] = s;
                    int ri = mf * 2 + (ci >> 1);
                    pm[ri] = fmaxf(pm[ri], s);
                }
#pragma unroll
        for (int i = 0; i < 4; i++) {
            pm[i] = fmaxf(pm[i], __shfl_xor_sync(~0u, pm[i], 1));
            pm[i] = fmaxf(pm[i], __shfl_xor_sync(~0u, pm[i], 2));
        }
        if (tc == 0) {
#pragma unroll
            for (int i = 0; i < 4; i++) {
                int row = wm * 32 + (i >> 1) * 16 + (i & 1) * 8 + gr;
                pmax[row * 4 + wn] = pm[i];
            }
        }
        __syncthreads();   // pmax visible

        float alpha[4];
#pragma unroll
        for (int i = 0; i < 4; i++) {
            int row = wm * 32 + (i >> 1) * 16 + (i & 1) * 8 + gr;
            float mt = fmaxf(fmaxf(pmax[row * 4 + 0], pmax[row * 4 + 1]),
                             fmaxf(pmax[row * 4 + 2], pmax[row * 4 + 3]));
            float m_new = fmaxf(m[i], mt);
            alpha[i] = __expf(m[i] - m_new);
            m[i] = m_new;
            l[i] *= alpha[i];
        }
#pragma unroll
        for (int mf = 0; mf < 2; mf++)
#pragma unroll
            for (int nf = 0; nf < 8; nf++)
#pragma unroll
                for (int ci = 0; ci < 4; ci++)
                    acc_o[mf][nf][ci] *= alpha[mf * 2 + (ci >> 1)];

        // ---------------- exp -> P (fp16) into smem ----------------
#pragma unroll
        for (int mf = 0; mf < 2; mf++)
#pragma unroll
            for (int nf = 0; nf < 4; nf++)
#pragma unroll
                for (int h = 0; h < 2; h++) {
                    int ri = mf * 2 + h;
                    float p0 = __expf(acc_s[mf][nf][h * 2 + 0] - m[ri]);
                    float p1 = __expf(acc_s[mf][nf][h * 2 + 1] - m[ri]);
                    l[ri] += p0 + p1;
                    int row = wm * 32 + mf * 16 + h * 8 + gr;
                    p32[row * 68 + wn * 16 + nf * 4 + tc] =
                        pk(__float2half(p0), __float2half(p1));
                }
        __syncthreads();   // P visible

        // ---------------- PV (all from smem, no syncs) ----------------
#pragma unroll
        for (int kc = 0; kc < 2; kc++)
#pragma unroll
            for (int ks = 0; ks < 4; ks++) {
                uint32 ah[2][4], bh[8][2];
#pragma unroll
                for (int mf = 0; mf < 2; mf++) {
                    int o = (wm * 32 + mf * 16 + gr) * 68 + kc * 32 + ks * 8 + tc;
                    ah[mf][0] = p32[o];      ah[mf][1] = p32[o + 8 * 68];
                    ah[mf][2] = p32[o + 4];  ah[mf][3] = p32[o + 8 * 68 + 4];
                }
#pragma unroll
                for (int nf = 0; nf < 8; nf++) {
                    int o = (wn * 64 + nf * 8 + gr) * 68 + kc * 32 + ks * 8 + tc;
                    bh[nf][0] = v32[o];  bh[nf][1] = v32[o + 4];
                }
#pragma unroll
                for (int mf = 0; mf < 2; mf++)
#pragma unroll
                    for (int nf = 0; nf < 8; nf++)
                        mma_f16(acc_o[mf][nf], ah[mf], bh[nf]);
            }
    }

    // ---------------- epilogue: reduce l, write partials ----------------
#pragma unroll
    for (int i = 0; i < 4; i++) {
        l[i] += __shfl_xor_sync(~0u, l[i], 1);
        l[i] += __shfl_xor_sync(~0u, l[i], 2);
    }
    __syncthreads();   // last PV reads + pmax reads done before reuse
    if (tc == 0) {
#pragma unroll
        for (int i = 0; i < 4; i++) {
            int row = wm * 32 + (i >> 1) * 16 + (i & 1) * 8 + gr;
            pmax[row * 4 + wn] = l[i];
        }
    }
    __syncthreads();

    const size_t pb = ((size_t)(b * 64 + qi) * 4 + c) * 64;
#pragma unroll
    for (int i = 0; i < 4; i++) {
        int row = wm * 32 + (i >> 1) * 16 + (i & 1) * 8 + gr;
        if (wn == 0 && tc == 0) {
            float lr = pmax[row * 4 + 0] + pmax[row * 4 + 1] +
                       pmax[row * 4 + 2] + pmax[row * 4 + 3];
            MPart[pb + row] = m[i];
            LPart[pb + row] = lr;
        }
    }
#pragma unroll
    for (int mf = 0; mf < 2; mf++)
#pragma unroll
        for (int h = 0; h < 2; h++) {
            int row = wm * 32 + mf * 16 + h * 8 + gr;
            float* orow = OPart + (pb + row) * 256;
#pragma unroll
            for (int nf = 0; nf < 8; nf++) {
                float2 v = make_float2(acc_o[mf][nf][h * 2 + 0],
                                       acc_o[mf][nf][h * 2 + 1]);
                *(float2*)(orow + wn * 64 + nf * 8 + 2 * tc) = v;
            }
        }
}

// ============================ kernel 6: combine =======================
__global__ __launch_bounds__(256) void combine_k(float* __restrict__ out) {
    const int t = threadIdx.x;
    const int R = blockIdx.x * 4 + (t >> 6);   // = q*2 + b
    const int q = R >> 1, b = R & 1;
    const int qi = q >> 6, r = q & 63;
    const int nc = (qi >> 4) + 1;
    const size_t cb = ((size_t)(b * 64 + qi) * 4) * 64 + r;

    float mx = -INFINITY;
    for (int c = 0; c < nc; c++) mx = fmaxf(mx, MPart[cb + (size_t)c * 64]);
    float w[4];
    float denom = 0.f;
    for (int c = 0; c < nc; c++) {
        w[c] = __expf(MPart[cb + (size_t)c * 64] - mx);
        denom += w[c] * LPart[cb + (size_t)c * 64];
    }
    const float inv = 1.f / denom;

    const int d = (t & 63) * 4;
    float4 acc = make_float4(0.f, 0.f, 0.f, 0.f);
    for (int c = 0; c < nc; c++) {
        const float4 v = *(const float4*)
            (OPart + (cb + (size_t)c * 64) * 256 + d);
        acc.x += w[c] * v.x; acc.y += w[c] * v.y;
        acc.z += w[c] * v.z; acc.w += w[c] * v.w;
    }
    acc.x *= inv; acc.y *= inv; acc.z *= inv; acc.w *= inv;
    *(float4*)(out + (size_t)R * 256 + d) = acc;
}

// ============================ launch ==================================
extern "C" void kernel_launch(void* const* d_in, const int* in_sizes, int n_in,
                              void* d_out, int out_size) {
    const float* x  = (const float*)d_in[0];
    const float* Wq = (const float*)d_in[2];
    const float* Wk = (const float*)d_in[3];
    const float* Wv = (const float*)d_in[4];
    float* out = (float*)d_out;

    cudaFuncSetAttribute(proj_mma, cudaFuncAttributeMaxDynamicSharedMemorySize, SMEM_GEMM);
    cudaFuncSetAttribute(fa_mma,   cudaFuncAttributeMaxDynamicSharedMemorySize, FSZ);

    cvt_x<<<2048, 256>>>(x);
    cvt_w<<<dim3(32, 8, 3), dim3(32, 8)>>>(Wq, Wk, Wv);
    proj_mma<<<dim3(128, 3), 256, SMEM_GEMM>>>();
    vtrans<<<dim3(64, 4, 2), 256>>>();
    fa_mma<<<dim3(160, 2), 256, FSZ>>>();
    combine_k<<<2048, 256>>>(out);
}

// round 10
// speedup vs baseline: 5.7895x; 1.0485x over previous
#include <cuda_runtime.h>
#include <cuda_fp16.h>
#include <math.h>
#include <stdint.h>

typedef __half f16;
typedef unsigned int uint32;

// ============================ scratch =================================
__device__ f16   Xh[8192 * 1024];
__device__ f16   Wth[3 * 256 * 1024], Wtl[3 * 256 * 1024];   // W^T [proj][n][k]
__device__ f16   Qh[2 * 4096 * 256];
__device__ f16   Kh[2 * 4096 * 256];
__device__ f16   Vh[2 * 4096 * 256];
__device__ float OPart[2ull * 64 * 4 * 64 * 256];            // split-K partials
__device__ float MPart[2 * 64 * 4 * 64];
__device__ float LPart[2 * 64 * 4 * 64];

// ============================ helpers =================================
__device__ __forceinline__ void split2(float x, f16& h, f16& l) {
    h = __float2half(x);
    l = __float2half(x - __half2float(h));
}
__device__ __forceinline__ uint32 pk(f16 a, f16 b) {
    __half2 v(a, b);
    return *(uint32*)&v;
}
__device__ __forceinline__ void mma_f16(float c[4], const uint32 a[4],
                                        const uint32 b[2]) {
    asm volatile(
        "mma.sync.aligned.m16n8k16.row.col.f32.f16.f16.f32 "
        "{%0,%1,%2,%3}, {%4,%5,%6,%7}, {%8,%9}, {%0,%1,%2,%3};"
        : "+f"(c[0]), "+f"(c[1]), "+f"(c[2]), "+f"(c[3])
        : "r"(a[0]), "r"(a[1]), "r"(a[2]), "r"(a[3]), "r"(b[0]), "r"(b[1]));
}
#define LDSM4(r0, r1, r2, r3, a)                                              \
    asm volatile("ldmatrix.sync.aligned.m8n8.x4.shared.b16 {%0,%1,%2,%3}, [%4];" \
                 : "=r"(r0), "=r"(r1), "=r"(r2), "=r"(r3) : "r"(a))
#define LDSM4T(r0, r1, r2, r3, a)                                             \
    asm volatile("ldmatrix.sync.aligned.m8n8.x4.trans.shared.b16 {%0,%1,%2,%3}, [%4];" \
                 : "=r"(r0), "=r"(r1), "=r"(r2), "=r"(r3) : "r"(a))

// ======================================================================
// GEMM core for projections: 2-pass fp16 split  C ≈ Ah·(Bh + Bl).
// ======================================================================
#define RS   72
#define PL   18432
#define SMEM_GEMM (3 * PL)

__device__ __forceinline__ void gemm128(
    const f16* __restrict__ Agh, size_t sA,
    const f16* __restrict__ Bgh, const f16* __restrict__ Bgl, size_t sB,
    int nchunk, char* smem, float acc[16][4])
{
    f16* sAh = (f16*)(smem);
    f16* sBh = (f16*)(smem + PL);
    f16* sBl = (f16*)(smem + 2 * PL);
    const int t = threadIdx.x;
    const int wid = t >> 5, lane = t & 31;
    const int wm = wid >> 2, wn = wid & 3;
    const int gr = lane >> 2, tc = lane & 3;

    int row[4], c8[4];
#pragma unroll
    for (int i = 0; i < 4; i++) { int u = t + 256 * i; row[i] = u >> 3; c8[i] = u & 7; }

    float4 p0[4], p2[4], p3[4];
#define GLOAD(k0) {                                                            \
    _Pragma("unroll") for (int i_ = 0; i_ < 4; i_++) {                         \
        p0[i_] = *(const float4*)(Agh + (size_t)row[i_] * sA + (k0) + c8[i_] * 8); \
        p2[i_] = *(const float4*)(Bgh + (size_t)row[i_] * sB + (k0) + c8[i_] * 8); \
        p3[i_] = *(const float4*)(Bgl + (size_t)row[i_] * sB + (k0) + c8[i_] * 8); \
    } }

    GLOAD(0);
    for (int ch = 0; ch < nchunk; ch++) {
        __syncthreads();
#pragma unroll
        for (int i = 0; i < 4; i++) {
            int off = row[i] * RS + c8[i] * 8;
            *(float4*)(sAh + off) = p0[i];
            *(float4*)(sBh + off) = p2[i];
            *(float4*)(sBl + off) = p3[i];
        }
        __syncthreads();
        if (ch + 1 < nchunk) GLOAD((ch + 1) * 64);

#pragma unroll
        for (int ks = 0; ks < 4; ks++) {
            uint32 ah[4][4], bh[4][2], bl[4][2];
#pragma unroll
            for (int mf = 0; mf < 4; mf++) {
                int o = (wm * 64 + mf * 16 + gr) * RS + ks * 16 + 2 * tc;
                ah[mf][0] = *(const uint32*)(sAh + o);
                ah[mf][1] = *(const uint32*)(sAh + o + 8 * RS);
                ah[mf][2] = *(const uint32*)(sAh + o + 8);
                ah[mf][3] = *(const uint32*)(sAh + o + 8 * RS + 8);
            }
#pragma unroll
            for (int nf = 0; nf < 4; nf++) {
                int o = (wn * 32 + nf * 8 + gr) * RS + ks * 16 + 2 * tc;
                bh[nf][0] = *(const uint32*)(sBh + o);
                bh[nf][1] = *(const uint32*)(sBh + o + 8);
                bl[nf][0] = *(const uint32*)(sBl + o);
                bl[nf][1] = *(const uint32*)(sBl + o + 8);
            }
#pragma unroll
            for (int mf = 0; mf < 4; mf++)
#pragma unroll
                for (int nf = 0; nf < 4; nf++) {
                    mma_f16(acc[mf * 4 + nf], ah[mf], bh[nf]);
                    mma_f16(acc[mf * 4 + nf], ah[mf], bl[nf]);
                }
        }
    }
#undef GLOAD
}

// ============================ kernel 1: convert X (hi only) ===========
__global__ __launch_bounds__(256) void cvt_x(const float* __restrict__ X) {
    const int N4 = 8192 * 1024 / 4;
    for (int i = blockIdx.x * 256 + threadIdx.x; i < N4; i += 2048 * 256) {
        float4 x = ((const float4*)X)[i];
        ((uint2*)Xh)[i] = make_uint2(
            pk(__float2half(x.x), __float2half(x.y)),
            pk(__float2half(x.z), __float2half(x.w)));
    }
}

// ============================ kernel 2: convert+transpose W ===========
__global__ void cvt_w(const float* __restrict__ Wq, const float* __restrict__ Wk,
                      const float* __restrict__ Wv) {
    __shared__ float tile[32][33];
    const int pj = blockIdx.z;
    const float* W = (pj == 0) ? Wq : (pj == 1) ? Wk : Wv;
    const int k0 = blockIdx.x * 32, n0 = blockIdx.y * 32;
    const int tx = threadIdx.x, ty = threadIdx.y;
#pragma unroll
    for (int i = 0; i < 4; i++)
        tile[ty + 8 * i][tx] = W[(k0 + ty + 8 * i) * 256 + n0 + tx];
    __syncthreads();
#pragma unroll
    for (int i = 0; i < 4; i++) {
        int n = n0 + ty + 8 * i;
        f16 h, l;
        split2(tile[tx][ty + 8 * i], h, l);
        Wth[pj * 262144 + n * 1024 + k0 + tx] = h;
        Wtl[pj * 262144 + n * 1024 + k0 + tx] = l;
    }
}

// ============================ kernel 3: projection GEMM ===============
__global__ __launch_bounds__(256) void proj_mma() {
    extern __shared__ char smem[];
    const int m0 = (blockIdx.x >> 1) * 128;
    const int nb = blockIdx.x & 1;
    const int pj = blockIdx.y;

    float acc[16][4];
#pragma unroll
    for (int i = 0; i < 16; i++)
#pragma unroll
        for (int j = 0; j < 4; j++) acc[i][j] = 0.f;

    gemm128(Xh + (size_t)m0 * 1024, 1024,
            Wth + pj * 262144 + (size_t)(nb * 128) * 1024,
            Wtl + pj * 262144 + (size_t)(nb * 128) * 1024, 1024,
            16, smem, acc);

    f16* dh = (pj == 0) ? Qh : (pj == 1) ? Kh : Vh;

    const int t = threadIdx.x, wid = t >> 5, lane = t & 31;
    const int wm = wid >> 2, wn = wid & 3;
    const int gr = lane >> 2, tc = lane & 3;
#pragma unroll
    for (int mf = 0; mf < 4; mf++)
#pragma unroll
        for (int nf = 0; nf < 4; nf++)
#pragma unroll
            for (int h = 0; h < 2; h++) {
                int m = m0 + wm * 64 + mf * 16 + gr + 8 * h;
                int n = nb * 128 + wn * 32 + nf * 8 + 2 * tc;
                int s = m >> 1, b = m & 1;
                float v0 = acc[mf * 4 + nf][2 * h];
                float v1 = acc[mf * 4 + nf][2 * h + 1];
                size_t o = ((size_t)b * 4096 + s) * 256 + n;
                *(uint32*)(dh + o) = pk(__float2half(v0), __float2half(v1));
            }
}

// ======================================================================
// Kernel 4: fused flash attention — resident tiles + ldmatrix frags.
// Q (64x256) persistent; K (128x256) and V (128x256, s-major) per k-tile.
// V B-frags via ldmatrix.trans (no V^T in HBM). fp16 1-pass mma.
// ======================================================================
#define SQ_  0                      // Q: 64 rows x 528 B   = 33792
#define SK_  33792                  // K: 128 rows x 528 B  = 67584
#define SV_  101376                 // V: 128 rows x 528 B  = 67584
#define SP_  168960                 // P: 64 x 272 B        = 17408
#define SMX_ 186368                 // 64 x 4 floats
#define FSZ  187392

__global__ __launch_bounds__(256) void fa_mma() {
    extern __shared__ char sm[];
    const int t = threadIdx.x, wid = t >> 5, lane = t & 31;
    const int wm = wid >> 2, wn = wid & 3;
    const int gr = lane >> 2, tc = lane & 3;
    const int b = blockIdx.y;
    const uint32 smb = (uint32)__cvta_generic_to_shared(sm);

    // ldmatrix per-thread address offsets
    const uint32 aoffQ = (lane & 15) * 528 + (lane >> 4) * 16;                 // A-frag (stride 528)
    const uint32 aoffP = (lane & 15) * 272 + (lane >> 4) * 16;                 // A-frag (stride 272)
    const uint32 boffK = ((lane & 7) + ((lane >> 4) & 1) * 8) * 528 + ((lane >> 3) & 1) * 16;
    const uint32 boffV = ((lane & 7) + ((lane >> 3) & 1) * 8) * 528 + ((lane >> 4) & 1) * 16;

    // chunk decode (reversed: biggest qi first); CHUNK = 8 key-tiles
    const int n = 159 - blockIdx.x;
    int qi, c;
    if (n < 16)      { qi = n;                  c = 0; }
    else if (n < 48) { int m_ = n - 16; qi = 16 + (m_ >> 1); c = m_ & 1; }
    else if (n < 96) { int m_ = n - 48; qi = 32 + m_ / 3;    c = m_ % 3; }
    else             { int m_ = n - 96; qi = 48 + (m_ >> 2); c = m_ & 3; }

    const int kt_diag = qi >> 1;
    const int kt0 = c * 8;
    const int kt1 = min(kt0 + 8, kt_diag + 1);
    const int q0 = qi * 64;

    uint32* p32 = (uint32*)(sm + SP_);
    float* pmax = (float*)(sm + SMX_);

    // ---- load Q once (64 x 256 f16) ----
#pragma unroll
    for (int i = 0; i < 8; i++) {
        int u = t + 256 * i, row = u >> 5, c16 = u & 31;
        *(float4*)(sm + SQ_ + row * 528 + c16 * 16) =
            *(const float4*)(Qh + ((size_t)(b * 4096 + q0 + row)) * 256 + c16 * 8);
    }

    float acc_o[2][8][4];
#pragma unroll
    for (int mf = 0; mf < 2; mf++)
#pragma unroll
        for (int nf = 0; nf < 8; nf++)
#pragma unroll
            for (int ci = 0; ci < 4; ci++) acc_o[mf][nf][ci] = 0.f;
    float m[4] = {-INFINITY, -INFINITY, -INFINITY, -INFINITY};
    float l[4] = {0.f, 0.f, 0.f, 0.f};

    for (int kt = kt0; kt < kt1; kt++) {
        const bool diag = (kt == kt_diag);

        __syncthreads();   // prior iter's smem reads done (covers Q stores, iter 0)
#pragma unroll
        for (int i = 0; i < 16; i++) {
            int u = t + 256 * i, row = u >> 5, c16 = u & 31;
            size_t g = ((size_t)(b * 4096 + kt * 128 + row)) * 256 + c16 * 8;
            *(float4*)(sm + SK_ + row * 528 + c16 * 16) = *(const float4*)(Kh + g);
            *(float4*)(sm + SV_ + row * 528 + c16 * 16) = *(const float4*)(Vh + g);
        }
        __syncthreads();

        // ---------------- S = Q K^T ----------------
        float acc_s[2][4][4];
#pragma unroll
        for (int mf = 0; mf < 2; mf++)
#pragma unroll
            for (int nf = 0; nf < 4; nf++)
#pragma unroll
                for (int ci = 0; ci < 4; ci++) acc_s[mf][nf][ci] = 0.f;

#pragma unroll
        for (int dc = 0; dc < 4; dc++)
#pragma unroll
            for (int ks = 0; ks < 4; ks++) {
                const uint32 kb = dc * 128 + ks * 32;
                uint32 ah[2][4], bh[4][2];
#pragma unroll
                for (int mf = 0; mf < 2; mf++)
                    LDSM4(ah[mf][0], ah[mf][1], ah[mf][2], ah[mf][3],
                          smb + SQ_ + (wm * 32 + mf * 16) * 528 + aoffQ + kb);
#pragma unroll
                for (int nfp = 0; nfp < 2; nfp++)
                    LDSM4(bh[2 * nfp][0], bh[2 * nfp][1],
                          bh[2 * nfp + 1][0], bh[2 * nfp + 1][1],
                          smb + SK_ + (wn * 32 + nfp * 16) * 528 + boffK + kb);
#pragma unroll
                for (int mf = 0; mf < 2; mf++)
#pragma unroll
                    for (int nf = 0; nf < 4; nf++)
                        mma_f16(acc_s[mf][nf], ah[mf], bh[nf]);
            }

        // ---------------- scale + mask + row-max ----------------
        float pm[4] = {-1e30f, -1e30f, -1e30f, -1e30f};
#pragma unroll
        for (int mf = 0; mf < 2; mf++)
#pragma unroll
            for (int nf = 0; nf < 4; nf++)
#pragma unroll
                for (int ci = 0; ci < 4; ci++) {
                    float s = acc_s[mf][nf][ci] * 0.0625f;
                    if (diag) {
                        int qg = q0 + wm * 32 + mf * 16 + gr + (ci >> 1) * 8;
                        int kg = kt * 128 + wn * 32 + nf * 8 + 2 * tc + (ci & 1);
                        if (kg > qg) s = -1e30f;
                    }
                    acc_s[mf][nf][ci] = s;
                    int ri = mf * 2 + (ci >> 1);
                    pm[ri] = fmaxf(pm[ri], s);
                }
#pragma unroll
        for (int i = 0; i < 4; i++) {
            pm[i] = fmaxf(pm[i], __shfl_xor_sync(~0u, pm[i], 1));
            pm[i] = fmaxf(pm[i], __shfl_xor_sync(~0u, pm[i], 2));
        }
        if (tc == 0) {
#pragma unroll
            for (int i = 0; i < 4; i++) {
                int row = wm * 32 + (i >> 1) * 16 + (i & 1) * 8 + gr;
                pmax[row * 4 + wn] = pm[i];
            }
        }
        __syncthreads();   // pmax visible

        float alpha[4];
#pragma unroll
        for (int i = 0; i < 4; i++) {
            int row = wm * 32 + (i >> 1) * 16 + (i & 1) * 8 + gr;
            float mt = fmaxf(fmaxf(pmax[row * 4 + 0], pmax[row * 4 + 1]),
                             fmaxf(pmax[row * 4 + 2], pmax[row * 4 + 3]));
            float m_new = fmaxf(m[i], mt);
            alpha[i] = __expf(m[i] - m_new);
            m[i] = m_new;
            l[i] *= alpha[i];
        }
#pragma unroll
        for (int mf = 0; mf < 2; mf++)
#pragma unroll
            for (int nf = 0; nf < 8; nf++)
#pragma unroll
                for (int ci = 0; ci < 4; ci++)
                    acc_o[mf][nf][ci] *= alpha[mf * 2 + (ci >> 1)];

        // ---------------- exp -> P (fp16) into smem ----------------
#pragma unroll
        for (int mf = 0; mf < 2; mf++)
#pragma unroll
            for (int nf = 0; nf < 4; nf++)
#pragma unroll
                for (int h = 0; h < 2; h++) {
                    int ri = mf * 2 + h;
                    float p0 = __expf(acc_s[mf][nf][h * 2 + 0] - m[ri]);
                    float p1 = __expf(acc_s[mf][nf][h * 2 + 1] - m[ri]);
                    l[ri] += p0 + p1;
                    int row = wm * 32 + mf * 16 + h * 8 + gr;
                    p32[row * 68 + wn * 16 + nf * 4 + tc] =
                        pk(__float2half(p0), __float2half(p1));
                }
        __syncthreads();   // P visible

        // ---------------- PV (V frags via ldmatrix.trans) ----------------
#pragma unroll
        for (int kc = 0; kc < 2; kc++)
#pragma unroll
            for (int ks = 0; ks < 4; ks++) {
                const uint32 sb_ = (kc * 64 + ks * 16) * 528;
                const uint32 pb_ = kc * 128 + ks * 32;
                uint32 ah[2][4], bh[8][2];
#pragma unroll
                for (int mf = 0; mf < 2; mf++)
                    LDSM4(ah[mf][0], ah[mf][1], ah[mf][2], ah[mf][3],
                          smb + SP_ + (wm * 32 + mf * 16) * 272 + aoffP + pb_);
#pragma unroll
                for (int nfp = 0; nfp < 4; nfp++)
                    LDSM4T(bh[2 * nfp][0], bh[2 * nfp][1],
                           bh[2 * nfp + 1][0], bh[2 * nfp + 1][1],
                           smb + SV_ + sb_ + boffV + wn * 128 + nfp * 32);
#pragma unroll
                for (int mf = 0; mf < 2; mf++)
#pragma unroll
                    for (int nf = 0; nf < 8; nf++)
                        mma_f16(acc_o[mf][nf], ah[mf], bh[nf]);
            }
    }

    // ---------------- epilogue: reduce l, write partials ----------------
#pragma unroll
    for (int i = 0; i < 4; i++) {
        l[i] += __shfl_xor_sync(~0u, l[i], 1);
        l[i] += __shfl_xor_sync(~0u, l[i], 2);
    }
    __syncthreads();   // last PV reads + pmax reads done before reuse
    if (tc == 0) {
#pragma unroll
        for (int i = 0; i < 4; i++) {
            int row = wm * 32 + (i >> 1) * 16 + (i & 1) * 8 + gr;
            pmax[row * 4 + wn] = l[i];
        }
    }
    __syncthreads();

    const size_t pb = ((size_t)(b * 64 + qi) * 4 + c) * 64;
#pragma unroll
    for (int i = 0; i < 4; i++) {
        int row = wm * 32 + (i >> 1) * 16 + (i & 1) * 8 + gr;
        if (wn == 0 && tc == 0) {
            float lr = pmax[row * 4 + 0] + pmax[row * 4 + 1] +
                       pmax[row * 4 + 2] + pmax[row * 4 + 3];
            MPart[pb + row] = m[i];
            LPart[pb + row] = lr;
        }
    }
#pragma unroll
    for (int mf = 0; mf < 2; mf++)
#pragma unroll
        for (int h = 0; h < 2; h++) {
            int row = wm * 32 + mf * 16 + h * 8 + gr;
            float* orow = OPart + (pb + row) * 256;
#pragma unroll
            for (int nf = 0; nf < 8; nf++) {
                float2 v = make_float2(acc_o[mf][nf][h * 2 + 0],
                                       acc_o[mf][nf][h * 2 + 1]);
                *(float2*)(orow + wn * 64 + nf * 8 + 2 * tc) = v;
            }
        }
}

// ============================ kernel 5: combine =======================
__global__ __launch_bounds__(256) void combine_k(float* __restrict__ out) {
    const int t = threadIdx.x;
    const int R = blockIdx.x * 4 + (t >> 6);   // = q*2 + b
    const int q = R >> 1, b = R & 1;
    const int qi = q >> 6, r = q & 63;
    const int nc = (qi >> 4) + 1;
    const size_t cb = ((size_t)(b * 64 + qi) * 4) * 64 + r;

    float mx = -INFINITY;
    for (int c = 0; c < nc; c++) mx = fmaxf(mx, MPart[cb + (size_t)c * 64]);
    float w[4];
    float denom = 0.f;
    for (int c = 0; c < nc; c++) {
        w[c] = __expf(MPart[cb + (size_t)c * 64] - mx);
        denom += w[c] * LPart[cb + (size_t)c * 64];
    }
    const float inv = 1.f / denom;

    const int d = (t & 63) * 4;
    float4 acc = make_float4(0.f, 0.f, 0.f, 0.f);
    for (int c = 0; c < nc; c++) {
        const float4 v = *(const float4*)
            (OPart + (cb + (size_t)c * 64) * 256 + d);
        acc.x += w[c] * v.x; acc.y += w[c] * v.y;
        acc.z += w[c] * v.z; acc.w += w[c] * v.w;
    }
    acc.x *= inv; acc.y *= inv; acc.z *= inv; acc.w *= inv;
    *(float4*)(out + (size_t)R * 256 + d) = acc;
}

// ============================ launch ==================================
extern "C" void kernel_launch(void* const* d_in, const int* in_sizes, int n_in,
                              void* d_out, int out_size) {
    const float* x  = (const float*)d_in[0];
    const float* Wq = (const float*)d_in[2];
    const float* Wk = (const float*)d_in[3];
    const float* Wv = (const float*)d_in[4];
    float* out = (float*)d_out;

    cudaFuncSetAttribute(proj_mma, cudaFuncAttributeMaxDynamicSharedMemorySize, SMEM_GEMM);
    cudaFuncSetAttribute(fa_mma,   cudaFuncAttributeMaxDynamicSharedMemorySize, FSZ);

    cvt_x<<<2048, 256>>>(x);
    cvt_w<<<dim3(32, 8, 3), dim3(32, 8)>>>(Wq, Wk, Wv);
    proj_mma<<<dim3(128, 3), 256, SMEM_GEMM>>>();
    fa_mma<<<dim3(160, 2), 256, FSZ>>>();
    combine_k<<<2048, 256>>>(out);
}